// round 12
// baseline (speedup 1.0000x reference)
#include <cuda_runtime.h>
#include <cuda_bf16.h>
#include <cstdint>
#include <cstddef>

constexpr int Bc = 2, Sq = 2048, HIDc = 4096, NHc = 32, NKVc = 8, HDc = 128;
constexpr int Kd = 4096;
constexpr int NQKV = 6144;  // fused projection width: 4096 Q + 1024 K + 1024 V

__device__ float g_Q[(size_t)Bc * NHc * Sq * HDc];
__device__ float g_K[(size_t)Bc * NKVc * Sq * HDc];
__device__ float g_V[(size_t)Bc * NKVc * Sq * HDc];
__device__ __nv_bfloat16 g_Ahi[(size_t)4096 * Kd];
__device__ __nv_bfloat16 g_Alo[(size_t)4096 * Kd];
__device__ __nv_bfloat16 g_Bhi[(size_t)NQKV * Kd];
__device__ __nv_bfloat16 g_Blo[(size_t)NQKV * Kd];

// ---------------------------------------------------------------------------
__device__ __forceinline__ uint32_t smem_u32(const void* p) {
    uint32_t a;
    asm("{ .reg .u64 t; cvta.to.shared.u64 t, %1; cvt.u32.u64 %0, t; }" : "=r"(a) : "l"(p));
    return a;
}
__device__ __forceinline__ float2 ffma2(float2 a, float2 b, float2 c) {
    unsigned long long ua = *reinterpret_cast<unsigned long long*>(&a);
    unsigned long long ub = *reinterpret_cast<unsigned long long*>(&b);
    unsigned long long uc = *reinterpret_cast<unsigned long long*>(&c);
    unsigned long long ud;
    asm("fma.rn.f32x2 %0, %1, %2, %3;" : "=l"(ud) : "l"(ua), "l"(ub), "l"(uc));
    return *reinterpret_cast<float2*>(&ud);
}
__device__ __forceinline__ void cp16(uint32_t d, const void* g) {
    asm volatile("cp.async.cg.shared.global [%0], [%1], 16;" :: "r"(d), "l"(g));
}
__device__ __forceinline__ void ldm4(uint32_t* r, uint32_t a) {
    asm volatile("ldmatrix.sync.aligned.m8n8.x4.shared.b16 {%0,%1,%2,%3}, [%4];"
        : "=r"(r[0]), "=r"(r[1]), "=r"(r[2]), "=r"(r[3]) : "r"(a));
}
__device__ __forceinline__ void mma16816(float* c, const uint32_t* a, uint32_t b0, uint32_t b1) {
    asm volatile("mma.sync.aligned.m16n8k16.row.col.f32.bf16.bf16.f32 "
        "{%0,%1,%2,%3}, {%4,%5,%6,%7}, {%8,%9}, {%0,%1,%2,%3};"
        : "+f"(c[0]), "+f"(c[1]), "+f"(c[2]), "+f"(c[3])
        : "r"(a[0]), "r"(a[1]), "r"(a[2]), "r"(a[3]), "r"(b0), "r"(b1));
}

// ---------------------------------------------------------------------------
// split / transpose-split building blocks
// ---------------------------------------------------------------------------
__device__ __forceinline__ void split_block(const float* __restrict__ x,
                                            __nv_bfloat16* __restrict__ hi,
                                            __nv_bfloat16* __restrict__ lo,
                                            size_t blk)
{
    size_t i = blk * 1024 + (size_t)threadIdx.x * 4;
    float4 v = *reinterpret_cast<const float4*>(x + i);
    __nv_bfloat16 h0 = __float2bfloat16(v.x), h1 = __float2bfloat16(v.y);
    __nv_bfloat16 h2 = __float2bfloat16(v.z), h3 = __float2bfloat16(v.w);
    *reinterpret_cast<__nv_bfloat162*>(hi + i)     = {h0, h1};
    *reinterpret_cast<__nv_bfloat162*>(hi + i + 2) = {h2, h3};
    *reinterpret_cast<__nv_bfloat162*>(lo + i) =
        {__float2bfloat16(v.x - __bfloat162float(h0)),
         __float2bfloat16(v.y - __bfloat162float(h1))};
    *reinterpret_cast<__nv_bfloat162*>(lo + i + 2) =
        {__float2bfloat16(v.z - __bfloat162float(h2)),
         __float2bfloat16(v.w - __bfloat162float(h3))};
}

__device__ __forceinline__ void tsplit_block(const float* __restrict__ W,
                                             __nv_bfloat16* __restrict__ Thi,
                                             __nv_bfloat16* __restrict__ Tlo,
                                             int N, int ro, int tile)
{
    __shared__ float t[32][33];
    int nt = N / 32;
    int n0 = (tile % nt) * 32, k0 = (tile / nt) * 32;
    int tx = threadIdx.x & 31, ty = threadIdx.x >> 5;
#pragma unroll
    for (int j = 0; j < 4; j++)
        t[ty + 8 * j][tx] = W[(size_t)(k0 + ty + 8 * j) * N + n0 + tx];
    __syncthreads();
#pragma unroll
    for (int j = 0; j < 4; j++) {
        float v = t[tx][ty + 8 * j];
        __nv_bfloat16 h = __float2bfloat16(v);
        size_t idx = (size_t)(ro + n0 + ty + 8 * j) * Kd + k0 + tx;
        Thi[idx] = h;
        Tlo[idx] = __float2bfloat16(v - __bfloat162float(h));
    }
}

// Fused prep: split(hidden) + transpose-split(Wq, Wk, Wv).
__global__ void prep_kernel(const float* __restrict__ hidden,
                            __nv_bfloat16* __restrict__ ahi, __nv_bfloat16* __restrict__ alo,
                            const float* __restrict__ Wq, const float* __restrict__ Wk,
                            const float* __restrict__ Wv,
                            __nv_bfloat16* __restrict__ bhi, __nv_bfloat16* __restrict__ blo)
{
    int b = blockIdx.x;
    if (b < 16384) { split_block(hidden, ahi, alo, b); return; }
    int tb = b - 16384;
    if (tb < 16384)      tsplit_block(Wq, bhi, blo, 4096, 0,    tb);
    else if (tb < 20480) tsplit_block(Wk, bhi, blo, 1024, 4096, tb - 16384);
    else                 tsplit_block(Wv, bhi, blo, 1024, 5120, tb - 20480);
}

__global__ void tsplit_kernel(const float* __restrict__ W, __nv_bfloat16* __restrict__ Thi,
                              __nv_bfloat16* __restrict__ Tlo)
{
    tsplit_block(W, Thi, Tlo, 4096, 0, blockIdx.x);
}

// ---------------------------------------------------------------------------
// bf16 mma.sync GEMM over virtual K' = 3*4096 — EXACT R8 mainloop (best).
// MODE 0: row-major C (N=4096), no bias.
// MODE 1: fused QKV epilogue (N=6144): col<4096 -> Q, <5120 -> K, else V.
// ---------------------------------------------------------------------------
constexpr int GSTAGE = 20480;
constexpr int GNSTG  = 4;
constexpr int GSMEM  = GNSTG * GSTAGE;  // 81920

template <int MODE>
__global__ __launch_bounds__(256, 2)
void gemm_mma(const __nv_bfloat16* __restrict__ Ahi, const __nv_bfloat16* __restrict__ Alo,
              const __nv_bfloat16* __restrict__ Bhi, const __nv_bfloat16* __restrict__ Blo,
              const float* __restrict__ bq, const float* __restrict__ bk,
              const float* __restrict__ bv,
              float* __restrict__ Cq, float* __restrict__ Ck, float* __restrict__ Cv,
              int N)
{
    extern __shared__ __align__(16) char smc[];
    const uint32_t sbase = smem_u32(smc);
    const int tid = threadIdx.x;
    const int warp = tid >> 5, lane = tid & 31;
    const int m0 = blockIdx.y * 128, n0 = blockIdx.x * 128;
    constexpr int NKI = 3 * (Kd / 32);

    auto issue = [&](int kc) {
        const int buf = kc % GNSTG;
        const uint32_t sb = sbase + buf * GSTAGE;
        const int seg = kc >> 7;
        const int k0 = (kc & 127) * 32;
        const __nv_bfloat16* Aseg = (seg == 1) ? Alo : Ahi;
        const __nv_bfloat16* Bseg = (seg == 2) ? Blo : Bhi;
#pragma unroll
        for (int j = 0; j < 4; j++) {
            int task = tid + j * 256;
            if (task < 512) {
                int row = task >> 2, ch = task & 3;
                cp16(sb + row * 80 + ch * 16,
                     Aseg + (size_t)(m0 + row) * Kd + k0 + ch * 8);
            } else {
                int t2 = task - 512;
                int row = t2 >> 2, ch = t2 & 3;
                cp16(sb + 10240 + row * 80 + ch * 16,
                     Bseg + (size_t)(n0 + row) * Kd + k0 + ch * 8);
            }
        }
        asm volatile("cp.async.commit_group;" ::: "memory");
    };

    const int wm = (warp >> 1) * 32, wn = (warp & 1) * 64;

    uint32_t fa[2][2][4];
    uint32_t fb[2][4][4];

    auto ldfrags = [&](int buf) {
        const uint32_t sA = sbase + buf * GSTAGE;
        const uint32_t sB = sA + 10240;
#pragma unroll
        for (int ks = 0; ks < 2; ks++) {
            const int kb = ks * 32;
#pragma unroll
            for (int mi = 0; mi < 2; mi++)
                ldm4(fa[ks][mi], sA + (wm + mi * 16 + (lane & 15)) * 80 + kb + (lane >> 4) * 16);
#pragma unroll
            for (int nb = 0; nb < 4; nb++)
                ldm4(fb[ks][nb], sB + (wn + nb * 16 + ((lane >> 4) << 3) + (lane & 7)) * 80
                                   + kb + ((lane >> 3) & 1) * 16);
        }
    };

    float acc[2][8][4];
#pragma unroll
    for (int mi = 0; mi < 2; mi++)
#pragma unroll
        for (int ni = 0; ni < 8; ni++)
#pragma unroll
            for (int r = 0; r < 4; r++) acc[mi][ni][r] = 0.f;

    issue(0);
    issue(1);
    issue(2);
    asm volatile("cp.async.wait_group 2;" ::: "memory");
    __syncthreads();
    ldfrags(0);
    issue(3);

    for (int kc = 0; kc < NKI; kc++) {
#pragma unroll
        for (int ks = 0; ks < 2; ks++)
#pragma unroll
            for (int mi = 0; mi < 2; mi++)
#pragma unroll
                for (int ni = 0; ni < 8; ni++)
                    mma16816(acc[mi][ni], fa[ks][mi],
                             fb[ks][ni >> 1][2 * (ni & 1)], fb[ks][ni >> 1][2 * (ni & 1) + 1]);

        if (kc + 1 < NKI) {
            asm volatile("cp.async.wait_group 2;" ::: "memory");
            __syncthreads();
            ldfrags((kc + 1) % GNSTG);
            if (kc + 4 < NKI) issue(kc + 4);
        }
    }

    // Epilogue
#pragma unroll
    for (int mi = 0; mi < 2; mi++) {
#pragma unroll
        for (int rg = 0; rg < 2; rg++) {
            const int m = m0 + wm + mi * 16 + rg * 8 + (lane >> 2);
            const int bidx = m >> 11, sidx = m & 2047;
#pragma unroll
            for (int ni = 0; ni < 8; ni++) {
                const int col = n0 + wn + ni * 8 + (lane & 3) * 2;
                float v0 = acc[mi][ni][rg * 2 + 0];
                float v1 = acc[mi][ni][rg * 2 + 1];
                float* dst;
                if (MODE == 0) {
                    dst = Cq + (size_t)m * N + col;
                } else {
                    const float* bs;
                    float* base;
                    int c2, heads;
                    if (col < 4096)      { bs = bq; base = Cq; c2 = col;        heads = NHc; }
                    else if (col < 5120) { bs = bk; base = Ck; c2 = col - 4096; heads = NKVc; }
                    else                 { bs = bv; base = Cv; c2 = col - 5120; heads = NKVc; }
                    v0 += __ldg(bs + c2);
                    v1 += __ldg(bs + c2 + 1);
                    int h = c2 >> 7, d = c2 & 127;
                    dst = base + (((size_t)bidx * heads + h) * Sq + sidx) * HDc + d;
                }
                *reinterpret_cast<float2*>(dst) = make_float2(v0, v1);
            }
        }
    }
}

// ---------------------------------------------------------------------------
// Fused RoPE for Q and K in one launch.
// ---------------------------------------------------------------------------
__global__ void rope2_kernel(float* __restrict__ q, float* __restrict__ k,
                             const float* __restrict__ cosp, const float* __restrict__ sinp)
{
    const int totQ = Bc * NHc * Sq * 64;
    const int totK = Bc * NKVc * Sq * 64;
    int i = blockIdx.x * blockDim.x + threadIdx.x;
    if (i >= totQ + totK) return;
    float* x;
    int heads;
    if (i < totQ) { x = q; heads = NHc; }
    else          { x = k; heads = NKVc; i -= totQ; }
    int dd = i & 63;
    int s = (i >> 6) & 2047;
    int bh = i >> 17;
    int h = bh % heads, b = bh / heads;
    size_t base = (((size_t)b * heads + h) * Sq + s) * HDc;
    size_t cbase = ((size_t)b * Sq + s) * HDc;
    float x1 = x[base + dd], x2 = x[base + dd + 64];
    float c1 = cosp[cbase + dd], c2 = cosp[cbase + dd + 64];
    float s1 = sinp[cbase + dd], s2 = sinp[cbase + dd + 64];
    x[base + dd]      = x1 * c1 - x2 * s1;
    x[base + dd + 64] = x2 * c2 + x1 * s2;
}

// ---------------------------------------------------------------------------
// Flash attention fp32, 512 threads (16 warps/SM), thread tile 4 rows x 8 cols.
// Epilogue fused with bf16 hi/lo split: writes directly into Ahi/Alo for the
// output projection (ctx buffer eliminated).
// grid (Sq/128, NH, B).
// ---------------------------------------------------------------------------
constexpr int FL_SMEM = (128 * 132 * 2 + 128 * 128) * 4;

__global__ __launch_bounds__(512, 1)
void flash_kernel(const float* __restrict__ Q, const float* __restrict__ Kg,
                  const float* __restrict__ Vg,
                  __nv_bfloat16* __restrict__ ahi, __nv_bfloat16* __restrict__ alo)
{
    constexpr int ST = 132;
    extern __shared__ __align__(16) float sm[];
    float* Qs = sm;
    float* Ks = sm + 128 * ST;
    float* Ps = Ks;
    float* Vs = sm + 2 * 128 * ST;

    const int tid = threadIdx.x;
    const int ti = tid >> 4;   // 0..31: row group (rows 4*ti .. 4*ti+3)
    const int tn = tid & 15;   // 0..15: column lane (cols tn + 16*j, j<8)
    const int b = blockIdx.z, h = blockIdx.y;
    const int kvh = h >> 2;
    const int q0 = blockIdx.x * 128;

    const float* qptr = Q  + (((size_t)b * NHc  + h)   * Sq + q0) * (size_t)HDc;
    const float* kptr = Kg + (((size_t)b * NKVc + kvh) * Sq) * (size_t)HDc;
    const float* vptr = Vg + (((size_t)b * NKVc + kvh) * Sq) * (size_t)HDc;

    // Q tile load (stride-132 rows)
#pragma unroll
    for (int i = 0; i < 8; i++) {
        int idx = tid + i * 512;
        int r = idx >> 5, c = (idx & 31) * 4;
        float4 q4 = *reinterpret_cast<const float4*>(qptr + (size_t)r * HDc + c);
        Qs[r * ST + c] = q4.x; Qs[r * ST + c + 1] = q4.y;
        Qs[r * ST + c + 2] = q4.z; Qs[r * ST + c + 3] = q4.w;
    }

    float2 O2[4][4];
    float mrow[4], lrow[4];
#pragma unroll
    for (int i = 0; i < 4; i++) {
        mrow[i] = -1e30f; lrow[i] = 0.f;
#pragma unroll
        for (int c = 0; c < 4; c++) O2[i][c] = make_float2(0.f, 0.f);
    }

    const float scale = 0.08838834764831845f;

    for (int n0 = 0; n0 < Sq; n0 += 128) {
        __syncthreads();
#pragma unroll
        for (int i = 0; i < 8; i++) {
            int idx = tid + i * 512;
            int r = idx >> 5, c = (idx & 31) * 4;
            float4 k4 = *reinterpret_cast<const float4*>(kptr + (size_t)(n0 + r) * HDc + c);
            Ks[r * ST + c] = k4.x; Ks[r * ST + c + 1] = k4.y;
            Ks[r * ST + c + 2] = k4.z; Ks[r * ST + c + 3] = k4.w;
            *reinterpret_cast<float4*>(Vs + r * 128 + c) =
                *reinterpret_cast<const float4*>(vptr + (size_t)(n0 + r) * HDc + c);
        }
        __syncthreads();

        float2 s2[4][4];
#pragma unroll
        for (int i = 0; i < 4; i++)
#pragma unroll
            for (int c = 0; c < 4; c++) s2[i][c] = make_float2(0.f, 0.f);

        for (int d = 0; d < HDc; d += 4) {
            float4 q4[4];
#pragma unroll
            for (int i = 0; i < 4; i++)
                q4[i] = *reinterpret_cast<const float4*>(&Qs[(4 * ti + i) * ST + d]);
#pragma unroll
            for (int c = 0; c < 4; c++) {
                float4 ka = *reinterpret_cast<const float4*>(&Ks[(tn + 32 * c) * ST + d]);
                float4 kb = *reinterpret_cast<const float4*>(&Ks[(tn + 32 * c + 16) * ST + d]);
#pragma unroll
                for (int i = 0; i < 4; i++) {
                    s2[i][c] = ffma2(make_float2(q4[i].x, q4[i].x), make_float2(ka.x, kb.x), s2[i][c]);
                    s2[i][c] = ffma2(make_float2(q4[i].y, q4[i].y), make_float2(ka.y, kb.y), s2[i][c]);
                    s2[i][c] = ffma2(make_float2(q4[i].z, q4[i].z), make_float2(ka.z, kb.z), s2[i][c]);
                    s2[i][c] = ffma2(make_float2(q4[i].w, q4[i].w), make_float2(ka.w, kb.w), s2[i][c]);
                }
            }
        }

        float corr[4];
#pragma unroll
        for (int i = 0; i < 4; i++) {
            float mt = fmaxf(fmaxf(fmaxf(s2[i][0].x, s2[i][0].y), fmaxf(s2[i][1].x, s2[i][1].y)),
                             fmaxf(fmaxf(s2[i][2].x, s2[i][2].y), fmaxf(s2[i][3].x, s2[i][3].y)));
            mt *= scale;
#pragma unroll
            for (int off = 1; off < 16; off <<= 1)
                mt = fmaxf(mt, __shfl_xor_sync(0xffffffffu, mt, off));
            float mnew = fmaxf(mrow[i], mt);
            corr[i] = __expf(mrow[i] - mnew);
            mrow[i] = mnew;
        }
#pragma unroll
        for (int i = 0; i < 4; i++) {
            float sum = 0.f;
#pragma unroll
            for (int c = 0; c < 4; c++) {
                float px = __expf(s2[i][c].x * scale - mrow[i]);
                float py = __expf(s2[i][c].y * scale - mrow[i]);
                s2[i][c].x = px; s2[i][c].y = py;
                sum += px + py;
            }
#pragma unroll
            for (int off = 1; off < 16; off <<= 1)
                sum += __shfl_xor_sync(0xffffffffu, sum, off);
            lrow[i] = lrow[i] * corr[i] + sum;
        }

        __syncthreads();  // all threads done reading Ks before P overwrites

#pragma unroll
        for (int i = 0; i < 4; i++) {
            int r = 4 * ti + i;
#pragma unroll
            for (int c = 0; c < 4; c++) {
                Ps[r * ST + tn + 32 * c]      = s2[i][c].x;
                Ps[r * ST + tn + 32 * c + 16] = s2[i][c].y;
            }
        }
        __syncwarp();  // PV reads only rows written by lanes sharing this ti

#pragma unroll
        for (int i = 0; i < 4; i++)
#pragma unroll
            for (int c = 0; c < 4; c++) { O2[i][c].x *= corr[i]; O2[i][c].y *= corr[i]; }

        for (int k = 0; k < 128; k += 4) {
            float4 p4[4];
#pragma unroll
            for (int i = 0; i < 4; i++)
                p4[i] = *reinterpret_cast<const float4*>(&Ps[(4 * ti + i) * ST + k]);
#pragma unroll
            for (int c = 0; c < 4; c++) {
                int ca = tn + 32 * c, cb = ca + 16;
                float2 v0 = make_float2(Vs[(k + 0) * 128 + ca], Vs[(k + 0) * 128 + cb]);
                float2 v1 = make_float2(Vs[(k + 1) * 128 + ca], Vs[(k + 1) * 128 + cb]);
                float2 v2 = make_float2(Vs[(k + 2) * 128 + ca], Vs[(k + 2) * 128 + cb]);
                float2 v3 = make_float2(Vs[(k + 3) * 128 + ca], Vs[(k + 3) * 128 + cb]);
#pragma unroll
                for (int i = 0; i < 4; i++) {
                    O2[i][c] = ffma2(make_float2(p4[i].x, p4[i].x), v0, O2[i][c]);
                    O2[i][c] = ffma2(make_float2(p4[i].y, p4[i].y), v1, O2[i][c]);
                    O2[i][c] = ffma2(make_float2(p4[i].z, p4[i].z), v2, O2[i][c]);
                    O2[i][c] = ffma2(make_float2(p4[i].w, p4[i].w), v3, O2[i][c]);
                }
            }
        }
    }

    // Epilogue: normalize + bf16 hi/lo split directly into A' for the O-proj.
    // A row = b*Sq + srow, col = h*128 + column.
#pragma unroll
    for (int i = 0; i < 4; i++) {
        float inv = 1.0f / lrow[i];
        int srow = q0 + 4 * ti + i;
        size_t arow = ((size_t)b * Sq + srow) * (size_t)HIDc + (size_t)h * HDc;
#pragma unroll
        for (int c = 0; c < 4; c++) {
            int ca = tn + 32 * c, cb = ca + 16;
            float va = O2[i][c].x * inv;
            float vb = O2[i][c].y * inv;
            __nv_bfloat16 ha = __float2bfloat16(va);
            __nv_bfloat16 hb = __float2bfloat16(vb);
            ahi[arow + ca] = ha;
            ahi[arow + cb] = hb;
            alo[arow + ca] = __float2bfloat16(va - __bfloat162float(ha));
            alo[arow + cb] = __float2bfloat16(vb - __bfloat162float(hb));
        }
    }
}

// ---------------------------------------------------------------------------
extern "C" void kernel_launch(void* const* d_in, const int* in_sizes, int n_in,
                              void* d_out, int out_size)
{
    const float* hidden = (const float*)d_in[0];
    const float* cosp   = (const float*)d_in[1];
    const float* sinp   = (const float*)d_in[2];
    const float* Wq     = (const float*)d_in[3];
    const float* bq     = (const float*)d_in[4];
    const float* Wk     = (const float*)d_in[5];
    const float* bk     = (const float*)d_in[6];
    const float* Wv     = (const float*)d_in[7];
    const float* bv     = (const float*)d_in[8];
    const float* Wo     = (const float*)d_in[9];
    float* out = (float*)d_out;

    float *qb, *kb, *vb;
    __nv_bfloat16 *ahi, *alo, *bhi, *blo;
    cudaGetSymbolAddress((void**)&qb, g_Q);
    cudaGetSymbolAddress((void**)&kb, g_K);
    cudaGetSymbolAddress((void**)&vb, g_V);
    cudaGetSymbolAddress((void**)&ahi, g_Ahi);
    cudaGetSymbolAddress((void**)&alo, g_Alo);
    cudaGetSymbolAddress((void**)&bhi, g_Bhi);
    cudaGetSymbolAddress((void**)&blo, g_Blo);

    cudaFuncSetAttribute(gemm_mma<0>, cudaFuncAttributeMaxDynamicSharedMemorySize, GSMEM);
    cudaFuncSetAttribute(gemm_mma<1>, cudaFuncAttributeMaxDynamicSharedMemorySize, GSMEM);
    cudaFuncSetAttribute(flash_kernel, cudaFuncAttributeMaxDynamicSharedMemorySize, FL_SMEM);

    // 1. prep: split(hidden) + transpose-split(Wq, Wk, Wv)
    prep_kernel<<<16384 + 16384 + 4096 + 4096, 256>>>(hidden, ahi, alo, Wq, Wk, Wv, bhi, blo);

    // 2. fused QKV projection (N = 6144)
    gemm_mma<1><<<dim3(NQKV / 128, 32), 256, GSMEM>>>(ahi, alo, bhi, blo,
                                                      bq, bk, bv, qb, kb, vb, NQKV);

    // 3. RoPE on Q and K in one launch
    {
        int tot = Bc * NHc * Sq * 64 + Bc * NKVc * Sq * 64;
        rope2_kernel<<<(tot + 255) / 256, 256>>>(qb, kb, cosp, sinp);
    }

    // 4. flash attention (epilogue writes A' hi/lo directly)  <-- profiled
    flash_kernel<<<dim3(Sq / 128, NHc, Bc), 512, FL_SMEM>>>(qb, kb, vb, ahi, alo);

    // 5-6. output projection
    tsplit_kernel<<<16384, 256>>>(Wo, bhi, blo);
    gemm_mma<0><<<dim3(32, 32), 256, GSMEM>>>(ahi, alo, bhi, blo,
                                              nullptr, nullptr, nullptr,
                                              out, nullptr, nullptr, 4096);
}

// round 13
// speedup vs baseline: 1.0342x; 1.0342x over previous
#include <cuda_runtime.h>
#include <cuda_bf16.h>
#include <cstdint>
#include <cstddef>

constexpr int Bc = 2, Sq = 2048, HIDc = 4096, NHc = 32, NKVc = 8, HDc = 128;
constexpr int Kd = 4096;
constexpr int NQKV = 6144;  // fused projection width: 4096 Q + 1024 K + 1024 V

__device__ float g_Q[(size_t)Bc * NHc * Sq * HDc];
__device__ float g_K[(size_t)Bc * NKVc * Sq * HDc];
__device__ float g_V[(size_t)Bc * NKVc * Sq * HDc];
__device__ __nv_bfloat16 g_Ahi[(size_t)4096 * Kd];
__device__ __nv_bfloat16 g_Alo[(size_t)4096 * Kd];
__device__ __nv_bfloat16 g_Bhi[(size_t)NQKV * Kd];
__device__ __nv_bfloat16 g_Blo[(size_t)NQKV * Kd];

// ---------------------------------------------------------------------------
__device__ __forceinline__ uint32_t smem_u32(const void* p) {
    uint32_t a;
    asm("{ .reg .u64 t; cvta.to.shared.u64 t, %1; cvt.u32.u64 %0, t; }" : "=r"(a) : "l"(p));
    return a;
}
__device__ __forceinline__ float2 ffma2(float2 a, float2 b, float2 c) {
    unsigned long long ua = *reinterpret_cast<unsigned long long*>(&a);
    unsigned long long ub = *reinterpret_cast<unsigned long long*>(&b);
    unsigned long long uc = *reinterpret_cast<unsigned long long*>(&c);
    unsigned long long ud;
    asm("fma.rn.f32x2 %0, %1, %2, %3;" : "=l"(ud) : "l"(ua), "l"(ub), "l"(uc));
    return *reinterpret_cast<float2*>(&ud);
}
__device__ __forceinline__ void cp16(uint32_t d, const void* g) {
    asm volatile("cp.async.cg.shared.global [%0], [%1], 16;" :: "r"(d), "l"(g));
}
__device__ __forceinline__ void ldm4(uint32_t* r, uint32_t a) {
    asm volatile("ldmatrix.sync.aligned.m8n8.x4.shared.b16 {%0,%1,%2,%3}, [%4];"
        : "=r"(r[0]), "=r"(r[1]), "=r"(r[2]), "=r"(r[3]) : "r"(a));
}
__device__ __forceinline__ void mma16816(float* c, const uint32_t* a, uint32_t b0, uint32_t b1) {
    asm volatile("mma.sync.aligned.m16n8k16.row.col.f32.bf16.bf16.f32 "
        "{%0,%1,%2,%3}, {%4,%5,%6,%7}, {%8,%9}, {%0,%1,%2,%3};"
        : "+f"(c[0]), "+f"(c[1]), "+f"(c[2]), "+f"(c[3])
        : "r"(a[0]), "r"(a[1]), "r"(a[2]), "r"(a[3]), "r"(b0), "r"(b1));
}

// ---------------------------------------------------------------------------
// split / transpose-split building blocks
// ---------------------------------------------------------------------------
__device__ __forceinline__ void split_block(const float* __restrict__ x,
                                            __nv_bfloat16* __restrict__ hi,
                                            __nv_bfloat16* __restrict__ lo,
                                            size_t blk)
{
    size_t i = blk * 1024 + (size_t)threadIdx.x * 4;
    float4 v = *reinterpret_cast<const float4*>(x + i);
    __nv_bfloat16 h0 = __float2bfloat16(v.x), h1 = __float2bfloat16(v.y);
    __nv_bfloat16 h2 = __float2bfloat16(v.z), h3 = __float2bfloat16(v.w);
    *reinterpret_cast<__nv_bfloat162*>(hi + i)     = {h0, h1};
    *reinterpret_cast<__nv_bfloat162*>(hi + i + 2) = {h2, h3};
    *reinterpret_cast<__nv_bfloat162*>(lo + i) =
        {__float2bfloat16(v.x - __bfloat162float(h0)),
         __float2bfloat16(v.y - __bfloat162float(h1))};
    *reinterpret_cast<__nv_bfloat162*>(lo + i + 2) =
        {__float2bfloat16(v.z - __bfloat162float(h2)),
         __float2bfloat16(v.w - __bfloat162float(h3))};
}

__device__ __forceinline__ void tsplit_block(const float* __restrict__ W,
                                             __nv_bfloat16* __restrict__ Thi,
                                             __nv_bfloat16* __restrict__ Tlo,
                                             int N, int ro, int tile)
{
    __shared__ float t[32][33];
    int nt = N / 32;
    int n0 = (tile % nt) * 32, k0 = (tile / nt) * 32;
    int tx = threadIdx.x & 31, ty = threadIdx.x >> 5;
#pragma unroll
    for (int j = 0; j < 4; j++)
        t[ty + 8 * j][tx] = W[(size_t)(k0 + ty + 8 * j) * N + n0 + tx];
    __syncthreads();
#pragma unroll
    for (int j = 0; j < 4; j++) {
        float v = t[tx][ty + 8 * j];
        __nv_bfloat16 h = __float2bfloat16(v);
        size_t idx = (size_t)(ro + n0 + ty + 8 * j) * Kd + k0 + tx;
        Thi[idx] = h;
        Tlo[idx] = __float2bfloat16(v - __bfloat162float(h));
    }
}

// Fused prep: split(hidden) + transpose-split(Wq, Wk, Wv).
__global__ void prep_kernel(const float* __restrict__ hidden,
                            __nv_bfloat16* __restrict__ ahi, __nv_bfloat16* __restrict__ alo,
                            const float* __restrict__ Wq, const float* __restrict__ Wk,
                            const float* __restrict__ Wv,
                            __nv_bfloat16* __restrict__ bhi, __nv_bfloat16* __restrict__ blo)
{
    int b = blockIdx.x;
    if (b < 16384) { split_block(hidden, ahi, alo, b); return; }
    int tb = b - 16384;
    if (tb < 16384)      tsplit_block(Wq, bhi, blo, 4096, 0,    tb);
    else if (tb < 20480) tsplit_block(Wk, bhi, blo, 1024, 4096, tb - 16384);
    else                 tsplit_block(Wv, bhi, blo, 1024, 5120, tb - 20480);
}

__global__ void tsplit_kernel(const float* __restrict__ W, __nv_bfloat16* __restrict__ Thi,
                              __nv_bfloat16* __restrict__ Tlo)
{
    tsplit_block(W, Thi, Tlo, 4096, 0, blockIdx.x);
}

// ---------------------------------------------------------------------------
// bf16 mma.sync GEMM over virtual K' = 3*4096 — EXACT R8 mainloop (best).
// MODE 0: row-major C (N=4096), no bias.
// MODE 1: fused QKV epilogue (N=6144): col<4096 -> Q, <5120 -> K, else V.
// ---------------------------------------------------------------------------
constexpr int GSTAGE = 20480;
constexpr int GNSTG  = 4;
constexpr int GSMEM  = GNSTG * GSTAGE;  // 81920

template <int MODE>
__global__ __launch_bounds__(256, 2)
void gemm_mma(const __nv_bfloat16* __restrict__ Ahi, const __nv_bfloat16* __restrict__ Alo,
              const __nv_bfloat16* __restrict__ Bhi, const __nv_bfloat16* __restrict__ Blo,
              const float* __restrict__ bq, const float* __restrict__ bk,
              const float* __restrict__ bv,
              float* __restrict__ Cq, float* __restrict__ Ck, float* __restrict__ Cv,
              int N)
{
    extern __shared__ __align__(16) char smc[];
    const uint32_t sbase = smem_u32(smc);
    const int tid = threadIdx.x;
    const int warp = tid >> 5, lane = tid & 31;
    const int m0 = blockIdx.y * 128, n0 = blockIdx.x * 128;
    constexpr int NKI = 3 * (Kd / 32);

    auto issue = [&](int kc) {
        const int buf = kc % GNSTG;
        const uint32_t sb = sbase + buf * GSTAGE;
        const int seg = kc >> 7;
        const int k0 = (kc & 127) * 32;
        const __nv_bfloat16* Aseg = (seg == 1) ? Alo : Ahi;
        const __nv_bfloat16* Bseg = (seg == 2) ? Blo : Bhi;
#pragma unroll
        for (int j = 0; j < 4; j++) {
            int task = tid + j * 256;
            if (task < 512) {
                int row = task >> 2, ch = task & 3;
                cp16(sb + row * 80 + ch * 16,
                     Aseg + (size_t)(m0 + row) * Kd + k0 + ch * 8);
            } else {
                int t2 = task - 512;
                int row = t2 >> 2, ch = t2 & 3;
                cp16(sb + 10240 + row * 80 + ch * 16,
                     Bseg + (size_t)(n0 + row) * Kd + k0 + ch * 8);
            }
        }
        asm volatile("cp.async.commit_group;" ::: "memory");
    };

    const int wm = (warp >> 1) * 32, wn = (warp & 1) * 64;

    uint32_t fa[2][2][4];
    uint32_t fb[2][4][4];

    auto ldfrags = [&](int buf) {
        const uint32_t sA = sbase + buf * GSTAGE;
        const uint32_t sB = sA + 10240;
#pragma unroll
        for (int ks = 0; ks < 2; ks++) {
            const int kb = ks * 32;
#pragma unroll
            for (int mi = 0; mi < 2; mi++)
                ldm4(fa[ks][mi], sA + (wm + mi * 16 + (lane & 15)) * 80 + kb + (lane >> 4) * 16);
#pragma unroll
            for (int nb = 0; nb < 4; nb++)
                ldm4(fb[ks][nb], sB + (wn + nb * 16 + ((lane >> 4) << 3) + (lane & 7)) * 80
                                   + kb + ((lane >> 3) & 1) * 16);
        }
    };

    float acc[2][8][4];
#pragma unroll
    for (int mi = 0; mi < 2; mi++)
#pragma unroll
        for (int ni = 0; ni < 8; ni++)
#pragma unroll
            for (int r = 0; r < 4; r++) acc[mi][ni][r] = 0.f;

    issue(0);
    issue(1);
    issue(2);
    asm volatile("cp.async.wait_group 2;" ::: "memory");
    __syncthreads();
    ldfrags(0);
    issue(3);

    for (int kc = 0; kc < NKI; kc++) {
#pragma unroll
        for (int ks = 0; ks < 2; ks++)
#pragma unroll
            for (int mi = 0; mi < 2; mi++)
#pragma unroll
                for (int ni = 0; ni < 8; ni++)
                    mma16816(acc[mi][ni], fa[ks][mi],
                             fb[ks][ni >> 1][2 * (ni & 1)], fb[ks][ni >> 1][2 * (ni & 1) + 1]);

        if (kc + 1 < NKI) {
            asm volatile("cp.async.wait_group 2;" ::: "memory");
            __syncthreads();
            ldfrags((kc + 1) % GNSTG);
            if (kc + 4 < NKI) issue(kc + 4);
        }
    }

    // Epilogue
#pragma unroll
    for (int mi = 0; mi < 2; mi++) {
#pragma unroll
        for (int rg = 0; rg < 2; rg++) {
            const int m = m0 + wm + mi * 16 + rg * 8 + (lane >> 2);
            const int bidx = m >> 11, sidx = m & 2047;
#pragma unroll
            for (int ni = 0; ni < 8; ni++) {
                const int col = n0 + wn + ni * 8 + (lane & 3) * 2;
                float v0 = acc[mi][ni][rg * 2 + 0];
                float v1 = acc[mi][ni][rg * 2 + 1];
                float* dst;
                if (MODE == 0) {
                    dst = Cq + (size_t)m * N + col;
                } else {
                    const float* bs;
                    float* base;
                    int c2, heads;
                    if (col < 4096)      { bs = bq; base = Cq; c2 = col;        heads = NHc; }
                    else if (col < 5120) { bs = bk; base = Ck; c2 = col - 4096; heads = NKVc; }
                    else                 { bs = bv; base = Cv; c2 = col - 5120; heads = NKVc; }
                    v0 += __ldg(bs + c2);
                    v1 += __ldg(bs + c2 + 1);
                    int h = c2 >> 7, d = c2 & 127;
                    dst = base + (((size_t)bidx * heads + h) * Sq + sidx) * HDc + d;
                }
                *reinterpret_cast<float2*>(dst) = make_float2(v0, v1);
            }
        }
    }
}

// ---------------------------------------------------------------------------
// Fused RoPE for Q and K in one launch.
// ---------------------------------------------------------------------------
__global__ void rope2_kernel(float* __restrict__ q, float* __restrict__ k,
                             const float* __restrict__ cosp, const float* __restrict__ sinp)
{
    const int totQ = Bc * NHc * Sq * 64;
    const int totK = Bc * NKVc * Sq * 64;
    int i = blockIdx.x * blockDim.x + threadIdx.x;
    if (i >= totQ + totK) return;
    float* x;
    int heads;
    if (i < totQ) { x = q; heads = NHc; }
    else          { x = k; heads = NKVc; i -= totQ; }
    int dd = i & 63;
    int s = (i >> 6) & 2047;
    int bh = i >> 17;
    int h = bh % heads, b = bh / heads;
    size_t base = (((size_t)b * heads + h) * Sq + s) * HDc;
    size_t cbase = ((size_t)b * Sq + s) * HDc;
    float x1 = x[base + dd], x2 = x[base + dd + 64];
    float c1 = cosp[cbase + dd], c2 = cosp[cbase + dd + 64];
    float s1 = sinp[cbase + dd], s2 = sinp[cbase + dd + 64];
    x[base + dd]      = x1 * c1 - x2 * s1;
    x[base + dd + 64] = x2 * c2 + x1 * s2;
}

// ---------------------------------------------------------------------------
// Flash attention fp32 — R11 geometry (256 threads, 8x8 thread tile; the
// measured best) + R12's fused epilogue (bf16 hi/lo split written directly
// into A' for the O-projection; ctx buffer eliminated).
// grid (Sq/128, NH, B).
// ---------------------------------------------------------------------------
constexpr int FL_SMEM = (128 * 132 * 2 + 128 * 128) * 4;

__global__ __launch_bounds__(256, 1)
void flash_kernel(const float* __restrict__ Q, const float* __restrict__ Kg,
                  const float* __restrict__ Vg,
                  __nv_bfloat16* __restrict__ ahi, __nv_bfloat16* __restrict__ alo)
{
    constexpr int ST = 132;
    extern __shared__ __align__(16) float sm[];
    float* Qs = sm;
    float* Ks = sm + 128 * ST;
    float* Ps = Ks;
    float* Vs = sm + 2 * 128 * ST;

    const int tid = threadIdx.x;
    const int ti = tid >> 4, tn = tid & 15;
    const int b = blockIdx.z, h = blockIdx.y;
    const int kvh = h >> 2;
    const int q0 = blockIdx.x * 128;

    const float* qptr = Q  + (((size_t)b * NHc  + h)   * Sq + q0) * (size_t)HDc;
    const float* kptr = Kg + (((size_t)b * NKVc + kvh) * Sq) * (size_t)HDc;
    const float* vptr = Vg + (((size_t)b * NKVc + kvh) * Sq) * (size_t)HDc;

#pragma unroll
    for (int i = 0; i < 16; i++) {
        int idx = tid + i * 256;
        int r = idx >> 5, c = (idx & 31) * 4;
        float4 q4 = *reinterpret_cast<const float4*>(qptr + (size_t)r * HDc + c);
        Qs[r * ST + c] = q4.x; Qs[r * ST + c + 1] = q4.y;
        Qs[r * ST + c + 2] = q4.z; Qs[r * ST + c + 3] = q4.w;
    }

    float2 O2[8][4];
    float mrow[8], lrow[8];
#pragma unroll
    for (int i = 0; i < 8; i++) {
        mrow[i] = -1e30f; lrow[i] = 0.f;
#pragma unroll
        for (int c = 0; c < 4; c++) O2[i][c] = make_float2(0.f, 0.f);
    }

    const float scale = 0.08838834764831845f;

    for (int n0 = 0; n0 < Sq; n0 += 128) {
        __syncthreads();
#pragma unroll
        for (int i = 0; i < 16; i++) {
            int idx = tid + i * 256;
            int r = idx >> 5, c = (idx & 31) * 4;
            float4 k4 = *reinterpret_cast<const float4*>(kptr + (size_t)(n0 + r) * HDc + c);
            Ks[r * ST + c] = k4.x; Ks[r * ST + c + 1] = k4.y;
            Ks[r * ST + c + 2] = k4.z; Ks[r * ST + c + 3] = k4.w;
            *reinterpret_cast<float4*>(Vs + r * 128 + c) =
                *reinterpret_cast<const float4*>(vptr + (size_t)(n0 + r) * HDc + c);
        }
        __syncthreads();

        float2 s2[8][4];
#pragma unroll
        for (int i = 0; i < 8; i++)
#pragma unroll
            for (int c = 0; c < 4; c++) s2[i][c] = make_float2(0.f, 0.f);

        for (int d = 0; d < HDc; d += 4) {
            float4 q4[8];
#pragma unroll
            for (int i = 0; i < 8; i++)
                q4[i] = *reinterpret_cast<const float4*>(&Qs[(8 * ti + i) * ST + d]);
#pragma unroll
            for (int c = 0; c < 4; c++) {
                float4 ka = *reinterpret_cast<const float4*>(&Ks[(tn + 16 * (2 * c)) * ST + d]);
                float4 kb = *reinterpret_cast<const float4*>(&Ks[(tn + 16 * (2 * c + 1)) * ST + d]);
#pragma unroll
                for (int i = 0; i < 8; i++) {
                    s2[i][c] = ffma2(make_float2(q4[i].x, q4[i].x), make_float2(ka.x, kb.x), s2[i][c]);
                    s2[i][c] = ffma2(make_float2(q4[i].y, q4[i].y), make_float2(ka.y, kb.y), s2[i][c]);
                    s2[i][c] = ffma2(make_float2(q4[i].z, q4[i].z), make_float2(ka.z, kb.z), s2[i][c]);
                    s2[i][c] = ffma2(make_float2(q4[i].w, q4[i].w), make_float2(ka.w, kb.w), s2[i][c]);
                }
            }
        }

        float corr[8];
#pragma unroll
        for (int i = 0; i < 8; i++) {
            float mt = fmaxf(fmaxf(fmaxf(s2[i][0].x, s2[i][0].y), fmaxf(s2[i][1].x, s2[i][1].y)),
                             fmaxf(fmaxf(s2[i][2].x, s2[i][2].y), fmaxf(s2[i][3].x, s2[i][3].y)));
            mt *= scale;
#pragma unroll
            for (int off = 1; off < 16; off <<= 1)
                mt = fmaxf(mt, __shfl_xor_sync(0xffffffffu, mt, off));
            float mnew = fmaxf(mrow[i], mt);
            corr[i] = __expf(mrow[i] - mnew);
            mrow[i] = mnew;
        }
#pragma unroll
        for (int i = 0; i < 8; i++) {
            float sum = 0.f;
#pragma unroll
            for (int c = 0; c < 4; c++) {
                float px = __expf(s2[i][c].x * scale - mrow[i]);
                float py = __expf(s2[i][c].y * scale - mrow[i]);
                s2[i][c].x = px; s2[i][c].y = py;
                sum += px + py;
            }
#pragma unroll
            for (int off = 1; off < 16; off <<= 1)
                sum += __shfl_xor_sync(0xffffffffu, sum, off);
            lrow[i] = lrow[i] * corr[i] + sum;
        }

        __syncthreads();

#pragma unroll
        for (int i = 0; i < 8; i++) {
            int r = 8 * ti + i;
#pragma unroll
            for (int c = 0; c < 4; c++) {
                Ps[r * ST + tn + 16 * (2 * c)]     = s2[i][c].x;
                Ps[r * ST + tn + 16 * (2 * c + 1)] = s2[i][c].y;
            }
        }
        __syncwarp();

#pragma unroll
        for (int i = 0; i < 8; i++)
#pragma unroll
            for (int c = 0; c < 4; c++) { O2[i][c].x *= corr[i]; O2[i][c].y *= corr[i]; }

        for (int k = 0; k < 128; k += 4) {
            float4 p4[8];
#pragma unroll
            for (int i = 0; i < 8; i++)
                p4[i] = *reinterpret_cast<const float4*>(&Ps[(8 * ti + i) * ST + k]);
#pragma unroll
            for (int c = 0; c < 4; c++) {
                int ca = tn + 16 * (2 * c), cb = tn + 16 * (2 * c + 1);
                float2 v0 = make_float2(Vs[(k + 0) * 128 + ca], Vs[(k + 0) * 128 + cb]);
                float2 v1 = make_float2(Vs[(k + 1) * 128 + ca], Vs[(k + 1) * 128 + cb]);
                float2 v2 = make_float2(Vs[(k + 2) * 128 + ca], Vs[(k + 2) * 128 + cb]);
                float2 v3 = make_float2(Vs[(k + 3) * 128 + ca], Vs[(k + 3) * 128 + cb]);
#pragma unroll
                for (int i = 0; i < 8; i++) {
                    O2[i][c] = ffma2(make_float2(p4[i].x, p4[i].x), v0, O2[i][c]);
                    O2[i][c] = ffma2(make_float2(p4[i].y, p4[i].y), v1, O2[i][c]);
                    O2[i][c] = ffma2(make_float2(p4[i].z, p4[i].z), v2, O2[i][c]);
                    O2[i][c] = ffma2(make_float2(p4[i].w, p4[i].w), v3, O2[i][c]);
                }
            }
        }
    }

    // Epilogue: normalize + bf16 hi/lo split directly into A' for the O-proj.
#pragma unroll
    for (int i = 0; i < 8; i++) {
        float inv = 1.0f / lrow[i];
        int srow = q0 + 8 * ti + i;
        size_t arow = ((size_t)b * Sq + srow) * (size_t)HIDc + (size_t)h * HDc;
#pragma unroll
        for (int c = 0; c < 4; c++) {
            int ca = tn + 16 * (2 * c), cb = tn + 16 * (2 * c + 1);
            float va = O2[i][c].x * inv;
            float vb = O2[i][c].y * inv;
            __nv_bfloat16 ha = __float2bfloat16(va);
            __nv_bfloat16 hb = __float2bfloat16(vb);
            ahi[arow + ca] = ha;
            ahi[arow + cb] = hb;
            alo[arow + ca] = __float2bfloat16(va - __bfloat162float(ha));
            alo[arow + cb] = __float2bfloat16(vb - __bfloat162float(hb));
        }
    }
}

// ---------------------------------------------------------------------------
extern "C" void kernel_launch(void* const* d_in, const int* in_sizes, int n_in,
                              void* d_out, int out_size)
{
    const float* hidden = (const float*)d_in[0];
    const float* cosp   = (const float*)d_in[1];
    const float* sinp   = (const float*)d_in[2];
    const float* Wq     = (const float*)d_in[3];
    const float* bq     = (const float*)d_in[4];
    const float* Wk     = (const float*)d_in[5];
    const float* bk     = (const float*)d_in[6];
    const float* Wv     = (const float*)d_in[7];
    const float* bv     = (const float*)d_in[8];
    const float* Wo     = (const float*)d_in[9];
    float* out = (float*)d_out;

    float *qb, *kb, *vb;
    __nv_bfloat16 *ahi, *alo, *bhi, *blo;
    cudaGetSymbolAddress((void**)&qb, g_Q);
    cudaGetSymbolAddress((void**)&kb, g_K);
    cudaGetSymbolAddress((void**)&vb, g_V);
    cudaGetSymbolAddress((void**)&ahi, g_Ahi);
    cudaGetSymbolAddress((void**)&alo, g_Alo);
    cudaGetSymbolAddress((void**)&bhi, g_Bhi);
    cudaGetSymbolAddress((void**)&blo, g_Blo);

    cudaFuncSetAttribute(gemm_mma<0>, cudaFuncAttributeMaxDynamicSharedMemorySize, GSMEM);
    cudaFuncSetAttribute(gemm_mma<1>, cudaFuncAttributeMaxDynamicSharedMemorySize, GSMEM);
    cudaFuncSetAttribute(flash_kernel, cudaFuncAttributeMaxDynamicSharedMemorySize, FL_SMEM);

    // 1. prep: split(hidden) + transpose-split(Wq, Wk, Wv)
    prep_kernel<<<16384 + 16384 + 4096 + 4096, 256>>>(hidden, ahi, alo, Wq, Wk, Wv, bhi, blo);

    // 2. fused QKV projection (N = 6144)
    gemm_mma<1><<<dim3(NQKV / 128, 32), 256, GSMEM>>>(ahi, alo, bhi, blo,
                                                      bq, bk, bv, qb, kb, vb, NQKV);

    // 3. RoPE on Q and K in one launch
    {
        int tot = Bc * NHc * Sq * 64 + Bc * NKVc * Sq * 64;
        rope2_kernel<<<(tot + 255) / 256, 256>>>(qb, kb, cosp, sinp);
    }

    // 4. flash attention (epilogue writes A' hi/lo directly)  <-- profiled
    flash_kernel<<<dim3(Sq / 128, NHc, Bc), 256, FL_SMEM>>>(qb, kb, vb, ahi, alo);

    // 5-6. output projection
    tsplit_kernel<<<16384, 256>>>(Wo, bhi, blo);
    gemm_mma<0><<<dim3(32, 32), 256, GSMEM>>>(ahi, alo, bhi, blo,
                                              nullptr, nullptr, nullptr,
                                              out, nullptr, nullptr, 4096);
}

// round 14
// speedup vs baseline: 1.3343x; 1.2902x over previous
#include <cuda_runtime.h>
#include <cuda_bf16.h>
#include <cstdint>
#include <cstddef>

constexpr int Bc = 2, Sq = 2048, HIDc = 4096, NHc = 32, NKVc = 8, HDc = 128;
constexpr int Kd = 4096;
constexpr int NQKV = 6144;

__device__ float g_Q[(size_t)Bc * NHc * Sq * HDc];
__device__ float g_K[(size_t)Bc * NKVc * Sq * HDc];
__device__ float g_V[(size_t)Bc * NKVc * Sq * HDc];
__device__ __nv_bfloat16 g_Ahi[(size_t)4096 * Kd];
__device__ __nv_bfloat16 g_Alo[(size_t)4096 * Kd];
__device__ __nv_bfloat16 g_Bhi[(size_t)NQKV * Kd];
__device__ __nv_bfloat16 g_Blo[(size_t)NQKV * Kd];

// ---------------------------------------------------------------------------
__device__ __forceinline__ uint32_t smem_u32(const void* p) {
    uint32_t a;
    asm("{ .reg .u64 t; cvta.to.shared.u64 t, %1; cvt.u32.u64 %0, t; }" : "=r"(a) : "l"(p));
    return a;
}
__device__ __forceinline__ void cp16(uint32_t d, const void* g) {
    asm volatile("cp.async.cg.shared.global [%0], [%1], 16;" :: "r"(d), "l"(g));
}
__device__ __forceinline__ void ldm4(uint32_t* r, uint32_t a) {
    asm volatile("ldmatrix.sync.aligned.m8n8.x4.shared.b16 {%0,%1,%2,%3}, [%4];"
        : "=r"(r[0]), "=r"(r[1]), "=r"(r[2]), "=r"(r[3]) : "r"(a));
}
__device__ __forceinline__ void ldm4t(uint32_t* r, uint32_t a) {
    asm volatile("ldmatrix.sync.aligned.m8n8.x4.trans.shared.b16 {%0,%1,%2,%3}, [%4];"
        : "=r"(r[0]), "=r"(r[1]), "=r"(r[2]), "=r"(r[3]) : "r"(a));
}
__device__ __forceinline__ void mma16816(float* c, const uint32_t* a, uint32_t b0, uint32_t b1) {
    asm volatile("mma.sync.aligned.m16n8k16.row.col.f32.bf16.bf16.f32 "
        "{%0,%1,%2,%3}, {%4,%5,%6,%7}, {%8,%9}, {%0,%1,%2,%3};"
        : "+f"(c[0]), "+f"(c[1]), "+f"(c[2]), "+f"(c[3])
        : "r"(a[0]), "r"(a[1]), "r"(a[2]), "r"(a[3]), "r"(b0), "r"(b1));
}
__device__ __forceinline__ uint32_t packbf(float lo, float hi) {
    uint32_t r;
    asm("cvt.rn.bf16x2.f32 %0, %1, %2;" : "=r"(r) : "f"(hi), "f"(lo));
    return r;
}

// ---------------------------------------------------------------------------
// split / transpose-split building blocks (unchanged)
// ---------------------------------------------------------------------------
__device__ __forceinline__ void split_block(const float* __restrict__ x,
                                            __nv_bfloat16* __restrict__ hi,
                                            __nv_bfloat16* __restrict__ lo,
                                            size_t blk)
{
    size_t i = blk * 1024 + (size_t)threadIdx.x * 4;
    float4 v = *reinterpret_cast<const float4*>(x + i);
    __nv_bfloat16 h0 = __float2bfloat16(v.x), h1 = __float2bfloat16(v.y);
    __nv_bfloat16 h2 = __float2bfloat16(v.z), h3 = __float2bfloat16(v.w);
    *reinterpret_cast<__nv_bfloat162*>(hi + i)     = {h0, h1};
    *reinterpret_cast<__nv_bfloat162*>(hi + i + 2) = {h2, h3};
    *reinterpret_cast<__nv_bfloat162*>(lo + i) =
        {__float2bfloat16(v.x - __bfloat162float(h0)),
         __float2bfloat16(v.y - __bfloat162float(h1))};
    *reinterpret_cast<__nv_bfloat162*>(lo + i + 2) =
        {__float2bfloat16(v.z - __bfloat162float(h2)),
         __float2bfloat16(v.w - __bfloat162float(h3))};
}

__device__ __forceinline__ void tsplit_block(const float* __restrict__ W,
                                             __nv_bfloat16* __restrict__ Thi,
                                             __nv_bfloat16* __restrict__ Tlo,
                                             int N, int ro, int tile)
{
    __shared__ float t[32][33];
    int nt = N / 32;
    int n0 = (tile % nt) * 32, k0 = (tile / nt) * 32;
    int tx = threadIdx.x & 31, ty = threadIdx.x >> 5;
#pragma unroll
    for (int j = 0; j < 4; j++)
        t[ty + 8 * j][tx] = W[(size_t)(k0 + ty + 8 * j) * N + n0 + tx];
    __syncthreads();
#pragma unroll
    for (int j = 0; j < 4; j++) {
        float v = t[tx][ty + 8 * j];
        __nv_bfloat16 h = __float2bfloat16(v);
        size_t idx = (size_t)(ro + n0 + ty + 8 * j) * Kd + k0 + tx;
        Thi[idx] = h;
        Tlo[idx] = __float2bfloat16(v - __bfloat162float(h));
    }
}

__global__ void prep_kernel(const float* __restrict__ hidden,
                            __nv_bfloat16* __restrict__ ahi, __nv_bfloat16* __restrict__ alo,
                            const float* __restrict__ Wq, const float* __restrict__ Wk,
                            const float* __restrict__ Wv,
                            __nv_bfloat16* __restrict__ bhi, __nv_bfloat16* __restrict__ blo)
{
    int b = blockIdx.x;
    if (b < 16384) { split_block(hidden, ahi, alo, b); return; }
    int tb = b - 16384;
    if (tb < 16384)      tsplit_block(Wq, bhi, blo, 4096, 0,    tb);
    else if (tb < 20480) tsplit_block(Wk, bhi, blo, 1024, 4096, tb - 16384);
    else                 tsplit_block(Wv, bhi, blo, 1024, 5120, tb - 20480);
}

__global__ void tsplit_kernel(const float* __restrict__ W, __nv_bfloat16* __restrict__ Thi,
                              __nv_bfloat16* __restrict__ Tlo)
{
    tsplit_block(W, Thi, Tlo, 4096, 0, blockIdx.x);
}

// ---------------------------------------------------------------------------
// bf16 mma.sync GEMM — EXACT R8 mainloop (unchanged, measured best).
// ---------------------------------------------------------------------------
constexpr int GSTAGE = 20480;
constexpr int GNSTG  = 4;
constexpr int GSMEM  = GNSTG * GSTAGE;

template <int MODE>
__global__ __launch_bounds__(256, 2)
void gemm_mma(const __nv_bfloat16* __restrict__ Ahi, const __nv_bfloat16* __restrict__ Alo,
              const __nv_bfloat16* __restrict__ Bhi, const __nv_bfloat16* __restrict__ Blo,
              const float* __restrict__ bq, const float* __restrict__ bk,
              const float* __restrict__ bv,
              float* __restrict__ Cq, float* __restrict__ Ck, float* __restrict__ Cv,
              int N)
{
    extern __shared__ __align__(16) char smc[];
    const uint32_t sbase = smem_u32(smc);
    const int tid = threadIdx.x;
    const int warp = tid >> 5, lane = tid & 31;
    const int m0 = blockIdx.y * 128, n0 = blockIdx.x * 128;
    constexpr int NKI = 3 * (Kd / 32);

    auto issue = [&](int kc) {
        const int buf = kc % GNSTG;
        const uint32_t sb = sbase + buf * GSTAGE;
        const int seg = kc >> 7;
        const int k0 = (kc & 127) * 32;
        const __nv_bfloat16* Aseg = (seg == 1) ? Alo : Ahi;
        const __nv_bfloat16* Bseg = (seg == 2) ? Blo : Bhi;
#pragma unroll
        for (int j = 0; j < 4; j++) {
            int task = tid + j * 256;
            if (task < 512) {
                int row = task >> 2, ch = task & 3;
                cp16(sb + row * 80 + ch * 16,
                     Aseg + (size_t)(m0 + row) * Kd + k0 + ch * 8);
            } else {
                int t2 = task - 512;
                int row = t2 >> 2, ch = t2 & 3;
                cp16(sb + 10240 + row * 80 + ch * 16,
                     Bseg + (size_t)(n0 + row) * Kd + k0 + ch * 8);
            }
        }
        asm volatile("cp.async.commit_group;" ::: "memory");
    };

    const int wm = (warp >> 1) * 32, wn = (warp & 1) * 64;

    uint32_t fa[2][2][4];
    uint32_t fb[2][4][4];

    auto ldfrags = [&](int buf) {
        const uint32_t sA = sbase + buf * GSTAGE;
        const uint32_t sB = sA + 10240;
#pragma unroll
        for (int ks = 0; ks < 2; ks++) {
            const int kb = ks * 32;
#pragma unroll
            for (int mi = 0; mi < 2; mi++)
                ldm4(fa[ks][mi], sA + (wm + mi * 16 + (lane & 15)) * 80 + kb + (lane >> 4) * 16);
#pragma unroll
            for (int nb = 0; nb < 4; nb++)
                ldm4(fb[ks][nb], sB + (wn + nb * 16 + ((lane >> 4) << 3) + (lane & 7)) * 80
                                   + kb + ((lane >> 3) & 1) * 16);
        }
    };

    float acc[2][8][4];
#pragma unroll
    for (int mi = 0; mi < 2; mi++)
#pragma unroll
        for (int ni = 0; ni < 8; ni++)
#pragma unroll
            for (int r = 0; r < 4; r++) acc[mi][ni][r] = 0.f;

    issue(0);
    issue(1);
    issue(2);
    asm volatile("cp.async.wait_group 2;" ::: "memory");
    __syncthreads();
    ldfrags(0);
    issue(3);

    for (int kc = 0; kc < NKI; kc++) {
#pragma unroll
        for (int ks = 0; ks < 2; ks++)
#pragma unroll
            for (int mi = 0; mi < 2; mi++)
#pragma unroll
                for (int ni = 0; ni < 8; ni++)
                    mma16816(acc[mi][ni], fa[ks][mi],
                             fb[ks][ni >> 1][2 * (ni & 1)], fb[ks][ni >> 1][2 * (ni & 1) + 1]);

        if (kc + 1 < NKI) {
            asm volatile("cp.async.wait_group 2;" ::: "memory");
            __syncthreads();
            ldfrags((kc + 1) % GNSTG);
            if (kc + 4 < NKI) issue(kc + 4);
        }
    }

#pragma unroll
    for (int mi = 0; mi < 2; mi++) {
#pragma unroll
        for (int rg = 0; rg < 2; rg++) {
            const int m = m0 + wm + mi * 16 + rg * 8 + (lane >> 2);
            const int bidx = m >> 11, sidx = m & 2047;
#pragma unroll
            for (int ni = 0; ni < 8; ni++) {
                const int col = n0 + wn + ni * 8 + (lane & 3) * 2;
                float v0 = acc[mi][ni][rg * 2 + 0];
                float v1 = acc[mi][ni][rg * 2 + 1];
                float* dst;
                if (MODE == 0) {
                    dst = Cq + (size_t)m * N + col;
                } else {
                    const float* bs;
                    float* base;
                    int c2, heads;
                    if (col < 4096)      { bs = bq; base = Cq; c2 = col;        heads = NHc; }
                    else if (col < 5120) { bs = bk; base = Ck; c2 = col - 4096; heads = NKVc; }
                    else                 { bs = bv; base = Cv; c2 = col - 5120; heads = NKVc; }
                    v0 += __ldg(bs + c2);
                    v1 += __ldg(bs + c2 + 1);
                    int h = c2 >> 7, d = c2 & 127;
                    dst = base + (((size_t)bidx * heads + h) * Sq + sidx) * HDc + d;
                }
                *reinterpret_cast<float2*>(dst) = make_float2(v0, v1);
            }
        }
    }
}

// ---------------------------------------------------------------------------
__global__ void rope2_kernel(float* __restrict__ q, float* __restrict__ k,
                             const float* __restrict__ cosp, const float* __restrict__ sinp)
{
    const int totQ = Bc * NHc * Sq * 64;
    const int totK = Bc * NKVc * Sq * 64;
    int i = blockIdx.x * blockDim.x + threadIdx.x;
    if (i >= totQ + totK) return;
    float* x;
    int heads;
    if (i < totQ) { x = q; heads = NHc; }
    else          { x = k; heads = NKVc; i -= totQ; }
    int dd = i & 63;
    int s = (i >> 6) & 2047;
    int bh = i >> 17;
    int h = bh % heads, b = bh / heads;
    size_t base = (((size_t)b * heads + h) * Sq + s) * HDc;
    size_t cbase = ((size_t)b * Sq + s) * HDc;
    float x1 = x[base + dd], x2 = x[base + dd + 64];
    float c1 = cosp[cbase + dd], c2 = cosp[cbase + dd + 64];
    float s1 = sinp[cbase + dd], s2 = sinp[cbase + dd + 64];
    x[base + dd]      = x1 * c1 - x2 * s1;
    x[base + dd + 64] = x2 * c2 + x1 * s2;
}

// ---------------------------------------------------------------------------
// Tensor-core flash attention (split-precision bf16 mma, fp32 accumulate).
// 256 threads, 8 warps; warp w owns q rows 16w..16w+15 of the 128-row tile.
// 3-pass QK^T (QhiKhi + QloKhi + QhiKlo) and 3-pass PV (PhiVhi+PloVhi+PhiVlo).
// V consumed via ldmatrix.trans (stored [key][d] like K, no SMEM transpose).
// Epilogue writes bf16 hi/lo of O directly into A' for the O-projection.
// grid (Sq/128, NH, B).
// ---------------------------------------------------------------------------
constexpr int FST = 136;                       // bf16 elems per SMEM row (272 B)
constexpr int FTILE = 128 * FST * 2;           // 34816 B per tile
constexpr int FL_SMEM = 6 * FTILE;             // 208896 B

__global__ __launch_bounds__(256, 1)
void flash_kernel(const float* __restrict__ Q, const float* __restrict__ Kg,
                  const float* __restrict__ Vg,
                  __nv_bfloat16* __restrict__ ahi, __nv_bfloat16* __restrict__ alo)
{
    extern __shared__ __align__(16) char fsm[];
    const uint32_t sb = smem_u32(fsm);
    const uint32_t sQhi = sb,             sQlo = sb + FTILE;
    const uint32_t sKhi = sb + 2 * FTILE, sKlo = sb + 3 * FTILE;
    const uint32_t sVhi = sb + 4 * FTILE, sVlo = sb + 5 * FTILE;

    const int tid = threadIdx.x;
    const int warp = tid >> 5, lane = tid & 31;
    const int b = blockIdx.z, h = blockIdx.y;
    const int kvh = h >> 2;
    const int q0 = blockIdx.x * 128;

    const float* qptr = Q  + (((size_t)b * NHc  + h)   * Sq + q0) * (size_t)HDc;
    const float* kptr = Kg + (((size_t)b * NKVc + kvh) * Sq) * (size_t)HDc;
    const float* vptr = Vg + (((size_t)b * NKVc + kvh) * Sq) * (size_t)HDc;

    // convert+store one float4 into hi/lo bf16 tiles at (r, c4)
    auto cvst = [&](uint32_t bhi_, uint32_t blo_, int r, int c4, float4 v) {
        __nv_bfloat16 h0 = __float2bfloat16(v.x), h1 = __float2bfloat16(v.y);
        __nv_bfloat16 h2 = __float2bfloat16(v.z), h3 = __float2bfloat16(v.w);
        uint32_t off = (uint32_t)(r * FST + c4) * 2;
        *reinterpret_cast<__nv_bfloat162*>(fsm + (bhi_ - sb) + off)     = {h0, h1};
        *reinterpret_cast<__nv_bfloat162*>(fsm + (bhi_ - sb) + off + 4) = {h2, h3};
        *reinterpret_cast<__nv_bfloat162*>(fsm + (blo_ - sb) + off) =
            {__float2bfloat16(v.x - __bfloat162float(h0)),
             __float2bfloat16(v.y - __bfloat162float(h1))};
        *reinterpret_cast<__nv_bfloat162*>(fsm + (blo_ - sb) + off + 4) =
            {__float2bfloat16(v.z - __bfloat162float(h2)),
             __float2bfloat16(v.w - __bfloat162float(h3))};
    };

    // Q tile -> Qhi/Qlo
#pragma unroll
    for (int i = 0; i < 16; i++) {
        int idx = tid + i * 256;
        int r = idx >> 5, c4 = (idx & 31) * 4;
        cvst(sQhi, sQlo, r, c4, *reinterpret_cast<const float4*>(qptr + (size_t)r * HDc + c4));
    }

    float of[16][4];
#pragma unroll
    for (int ni = 0; ni < 16; ni++)
#pragma unroll
        for (int r = 0; r < 4; r++) of[ni][r] = 0.f;
    float mrow[2] = {-1e30f, -1e30f};
    float lrow[2] = {0.f, 0.f};

    const float scale = 0.08838834764831845f;

    // fragment base addresses (byte offsets within tiles)
    const uint32_t aoff = (uint32_t)((16 * warp + (lane & 15)) * FST) * 2 + (lane >> 4) * 16;
    const uint32_t boff = (uint32_t)((((lane >> 4) << 3) + (lane & 7)) * FST) * 2
                        + ((lane >> 3) & 1) * 16;
    const uint32_t toff = (uint32_t)((((lane >> 3) & 1) * 8 + (lane & 7)) * FST) * 2
                        + (lane >> 4) * 16;

    for (int n0 = 0; n0 < Sq; n0 += 128) {
        __syncthreads();  // prior PV done (and Q stores on first iter)
#pragma unroll
        for (int i = 0; i < 16; i++) {
            int idx = tid + i * 256;
            int r = idx >> 5, c4 = (idx & 31) * 4;
            cvst(sKhi, sKlo, r, c4,
                 *reinterpret_cast<const float4*>(kptr + (size_t)(n0 + r) * HDc + c4));
            cvst(sVhi, sVlo, r, c4,
                 *reinterpret_cast<const float4*>(vptr + (size_t)(n0 + r) * HDc + c4));
        }
        __syncthreads();

        // ---- S = Q K^T (3 passes) ----
        float sf[16][4];
#pragma unroll
        for (int ni = 0; ni < 16; ni++)
#pragma unroll
            for (int r = 0; r < 4; r++) sf[ni][r] = 0.f;

#pragma unroll
        for (int pass = 0; pass < 3; pass++) {
            const uint32_t Ab = (pass == 1) ? sQlo : sQhi;
            const uint32_t Bb = (pass == 2) ? sKlo : sKhi;
#pragma unroll
            for (int s = 0; s < 8; s++) {
                uint32_t a[4];
                ldm4(a, Ab + aoff + s * 32);
#pragma unroll
                for (int nb = 0; nb < 8; nb++) {
                    uint32_t bb[4];
                    ldm4(bb, Bb + boff + (uint32_t)(nb * 16 * FST) * 2 + s * 32);
                    mma16816(sf[2 * nb],     a, bb[0], bb[1]);
                    mma16816(sf[2 * nb + 1], a, bb[2], bb[3]);
                }
            }
        }

        // ---- online softmax (rows lane>>2 and lane>>2 + 8) ----
        float corr[2];
#pragma unroll
        for (int half = 0; half < 2; half++) {
            float mt = -1e30f;
#pragma unroll
            for (int ni = 0; ni < 16; ni++)
                mt = fmaxf(mt, fmaxf(sf[ni][2 * half], sf[ni][2 * half + 1]));
            mt *= scale;
            mt = fmaxf(mt, __shfl_xor_sync(0xffffffffu, mt, 1));
            mt = fmaxf(mt, __shfl_xor_sync(0xffffffffu, mt, 2));
            float mnew = fmaxf(mrow[half], mt);
            corr[half] = __expf(mrow[half] - mnew);
            mrow[half] = mnew;
            float sum = 0.f;
#pragma unroll
            for (int ni = 0; ni < 16; ni++) {
                float p0 = __expf(sf[ni][2 * half]     * scale - mnew);
                float p1 = __expf(sf[ni][2 * half + 1] * scale - mnew);
                sf[ni][2 * half]     = p0;
                sf[ni][2 * half + 1] = p1;
                sum += p0 + p1;
            }
            sum += __shfl_xor_sync(0xffffffffu, sum, 1);
            sum += __shfl_xor_sync(0xffffffffu, sum, 2);
            lrow[half] = lrow[half] * corr[half] + sum;
        }

        // rescale O
#pragma unroll
        for (int ni = 0; ni < 16; ni++) {
            of[ni][0] *= corr[0]; of[ni][1] *= corr[0];
            of[ni][2] *= corr[1]; of[ni][3] *= corr[1];
        }

        // ---- convert P -> A fragments (hi/lo), in-register ----
        uint32_t phi[8][4], plo[8][4];
#pragma unroll
        for (int s = 0; s < 8; s++) {
#pragma unroll
            for (int q = 0; q < 4; q++) {
                // q: 0 -> cell 2s rows (c0,c1); 1 -> cell 2s rows+8 (c2,c3);
                //    2 -> cell 2s+1 (c0,c1);   3 -> cell 2s+1 (c2,c3)
                int cell = 2 * s + (q >> 1);
                float p0 = sf[cell][(q & 1) * 2];
                float p1 = sf[cell][(q & 1) * 2 + 1];
                uint32_t hpk = packbf(p0, p1);
                __nv_bfloat162 hb = *reinterpret_cast<__nv_bfloat162*>(&hpk);
                phi[s][q] = hpk;
                plo[s][q] = packbf(p0 - __bfloat162float(hb.x),
                                   p1 - __bfloat162float(hb.y));
            }
        }

        // ---- O += P V (3 passes) ----
#pragma unroll
        for (int pass = 0; pass < 3; pass++) {
            const uint32_t (*Af)[4] = (pass == 1) ? plo : phi;
            const uint32_t Bb = (pass == 2) ? sVlo : sVhi;
#pragma unroll
            for (int s = 0; s < 8; s++) {
#pragma unroll
                for (int nb = 0; nb < 8; nb++) {
                    uint32_t bb[4];
                    ldm4t(bb, Bb + toff + (uint32_t)(16 * s * FST) * 2 + (uint32_t)(nb * 16) * 2);
                    mma16816(of[2 * nb],     Af[s], bb[0], bb[1]);
                    mma16816(of[2 * nb + 1], Af[s], bb[2], bb[3]);
                }
            }
        }
    }

    // ---- epilogue: normalize + bf16 hi/lo split into A' ----
    float inv0 = 1.0f / lrow[0], inv1 = 1.0f / lrow[1];
    int r0 = q0 + 16 * warp + (lane >> 2);
    int r1 = r0 + 8;
    size_t arow0 = ((size_t)b * Sq + r0) * (size_t)HIDc + (size_t)h * HDc;
    size_t arow1 = ((size_t)b * Sq + r1) * (size_t)HIDc + (size_t)h * HDc;
#pragma unroll
    for (int ni = 0; ni < 16; ni++) {
        int d0 = 8 * ni + (lane & 3) * 2;
        {
            float v0 = of[ni][0] * inv0, v1 = of[ni][1] * inv0;
            uint32_t hp = packbf(v0, v1);
            __nv_bfloat162 hb = *reinterpret_cast<__nv_bfloat162*>(&hp);
            uint32_t lp = packbf(v0 - __bfloat162float(hb.x), v1 - __bfloat162float(hb.y));
            *reinterpret_cast<uint32_t*>(ahi + arow0 + d0) = hp;
            *reinterpret_cast<uint32_t*>(alo + arow0 + d0) = lp;
        }
        {
            float v0 = of[ni][2] * inv1, v1 = of[ni][3] * inv1;
            uint32_t hp = packbf(v0, v1);
            __nv_bfloat162 hb = *reinterpret_cast<__nv_bfloat162*>(&hp);
            uint32_t lp = packbf(v0 - __bfloat162float(hb.x), v1 - __bfloat162float(hb.y));
            *reinterpret_cast<uint32_t*>(ahi + arow1 + d0) = hp;
            *reinterpret_cast<uint32_t*>(alo + arow1 + d0) = lp;
        }
    }
}

// ---------------------------------------------------------------------------
extern "C" void kernel_launch(void* const* d_in, const int* in_sizes, int n_in,
                              void* d_out, int out_size)
{
    const float* hidden = (const float*)d_in[0];
    const float* cosp   = (const float*)d_in[1];
    const float* sinp   = (const float*)d_in[2];
    const float* Wq     = (const float*)d_in[3];
    const float* bq     = (const float*)d_in[4];
    const float* Wk     = (const float*)d_in[5];
    const float* bk     = (const float*)d_in[6];
    const float* Wv     = (const float*)d_in[7];
    const float* bv     = (const float*)d_in[8];
    const float* Wo     = (const float*)d_in[9];
    float* out = (float*)d_out;

    float *qb, *kb, *vb;
    __nv_bfloat16 *ahi, *alo, *bhi, *blo;
    cudaGetSymbolAddress((void**)&qb, g_Q);
    cudaGetSymbolAddress((void**)&kb, g_K);
    cudaGetSymbolAddress((void**)&vb, g_V);
    cudaGetSymbolAddress((void**)&ahi, g_Ahi);
    cudaGetSymbolAddress((void**)&alo, g_Alo);
    cudaGetSymbolAddress((void**)&bhi, g_Bhi);
    cudaGetSymbolAddress((void**)&blo, g_Blo);

    cudaFuncSetAttribute(gemm_mma<0>, cudaFuncAttributeMaxDynamicSharedMemorySize, GSMEM);
    cudaFuncSetAttribute(gemm_mma<1>, cudaFuncAttributeMaxDynamicSharedMemorySize, GSMEM);
    cudaFuncSetAttribute(flash_kernel, cudaFuncAttributeMaxDynamicSharedMemorySize, FL_SMEM);

    // 1. prep
    prep_kernel<<<16384 + 16384 + 4096 + 4096, 256>>>(hidden, ahi, alo, Wq, Wk, Wv, bhi, blo);

    // 2. fused QKV projection
    gemm_mma<1><<<dim3(NQKV / 128, 32), 256, GSMEM>>>(ahi, alo, bhi, blo,
                                                      bq, bk, bv, qb, kb, vb, NQKV);

    // 3. RoPE
    {
        int tot = Bc * NHc * Sq * 64 + Bc * NKVc * Sq * 64;
        rope2_kernel<<<(tot + 255) / 256, 256>>>(qb, kb, cosp, sinp);
    }

    // 4. tensor-core flash attention  <-- profiled
    flash_kernel<<<dim3(Sq / 128, NHc, Bc), 256, FL_SMEM>>>(qb, kb, vb, ahi, alo);

    // 5-6. output projection
    tsplit_kernel<<<16384, 256>>>(Wo, bhi, blo);
    gemm_mma<0><<<dim3(32, 32), 256, GSMEM>>>(ahi, alo, bhi, blo,
                                              nullptr, nullptr, nullptr,
                                              out, nullptr, nullptr, 4096);
}

// round 15
// speedup vs baseline: 1.5373x; 1.1522x over previous
#include <cuda_runtime.h>
#include <cuda_bf16.h>
#include <cstdint>
#include <cstddef>

constexpr int Bc = 2, Sq = 2048, HIDc = 4096, NHc = 32, NKVc = 8, HDc = 128;
constexpr int Kd = 4096;
constexpr int NQKV = 6144;

__device__ float g_Q[(size_t)Bc * NHc * Sq * HDc];
__device__ float g_K[(size_t)Bc * NKVc * Sq * HDc];
__device__ float g_V[(size_t)Bc * NKVc * Sq * HDc];
__device__ __nv_bfloat16 g_Ahi[(size_t)4096 * Kd];
__device__ __nv_bfloat16 g_Alo[(size_t)4096 * Kd];
__device__ __nv_bfloat16 g_Bhi[(size_t)NQKV * Kd];
__device__ __nv_bfloat16 g_Blo[(size_t)NQKV * Kd];

// ---------------------------------------------------------------------------
__device__ __forceinline__ uint32_t smem_u32(const void* p) {
    uint32_t a;
    asm("{ .reg .u64 t; cvta.to.shared.u64 t, %1; cvt.u32.u64 %0, t; }" : "=r"(a) : "l"(p));
    return a;
}
__device__ __forceinline__ void cp16(uint32_t d, const void* g) {
    asm volatile("cp.async.cg.shared.global [%0], [%1], 16;" :: "r"(d), "l"(g));
}
__device__ __forceinline__ void ldm4(uint32_t* r, uint32_t a) {
    asm volatile("ldmatrix.sync.aligned.m8n8.x4.shared.b16 {%0,%1,%2,%3}, [%4];"
        : "=r"(r[0]), "=r"(r[1]), "=r"(r[2]), "=r"(r[3]) : "r"(a));
}
__device__ __forceinline__ void ldm4t(uint32_t* r, uint32_t a) {
    asm volatile("ldmatrix.sync.aligned.m8n8.x4.trans.shared.b16 {%0,%1,%2,%3}, [%4];"
        : "=r"(r[0]), "=r"(r[1]), "=r"(r[2]), "=r"(r[3]) : "r"(a));
}
__device__ __forceinline__ void mma16816(float* c, const uint32_t* a, uint32_t b0, uint32_t b1) {
    asm volatile("mma.sync.aligned.m16n8k16.row.col.f32.bf16.bf16.f32 "
        "{%0,%1,%2,%3}, {%4,%5,%6,%7}, {%8,%9}, {%0,%1,%2,%3};"
        : "+f"(c[0]), "+f"(c[1]), "+f"(c[2]), "+f"(c[3])
        : "r"(a[0]), "r"(a[1]), "r"(a[2]), "r"(a[3]), "r"(b0), "r"(b1));
}
__device__ __forceinline__ uint32_t packbf(float lo, float hi) {
    uint32_t r;
    asm("cvt.rn.bf16x2.f32 %0, %1, %2;" : "=r"(r) : "f"(hi), "f"(lo));
    return r;
}

// ---------------------------------------------------------------------------
// split / transpose-split building blocks (unchanged)
// ---------------------------------------------------------------------------
__device__ __forceinline__ void split_block(const float* __restrict__ x,
                                            __nv_bfloat16* __restrict__ hi,
                                            __nv_bfloat16* __restrict__ lo,
                                            size_t blk)
{
    size_t i = blk * 1024 + (size_t)threadIdx.x * 4;
    float4 v = *reinterpret_cast<const float4*>(x + i);
    __nv_bfloat16 h0 = __float2bfloat16(v.x), h1 = __float2bfloat16(v.y);
    __nv_bfloat16 h2 = __float2bfloat16(v.z), h3 = __float2bfloat16(v.w);
    *reinterpret_cast<__nv_bfloat162*>(hi + i)     = {h0, h1};
    *reinterpret_cast<__nv_bfloat162*>(hi + i + 2) = {h2, h3};
    *reinterpret_cast<__nv_bfloat162*>(lo + i) =
        {__float2bfloat16(v.x - __bfloat162float(h0)),
         __float2bfloat16(v.y - __bfloat162float(h1))};
    *reinterpret_cast<__nv_bfloat162*>(lo + i + 2) =
        {__float2bfloat16(v.z - __bfloat162float(h2)),
         __float2bfloat16(v.w - __bfloat162float(h3))};
}

__device__ __forceinline__ void tsplit_block(const float* __restrict__ W,
                                             __nv_bfloat16* __restrict__ Thi,
                                             __nv_bfloat16* __restrict__ Tlo,
                                             int N, int ro, int tile)
{
    __shared__ float t[32][33];
    int nt = N / 32;
    int n0 = (tile % nt) * 32, k0 = (tile / nt) * 32;
    int tx = threadIdx.x & 31, ty = threadIdx.x >> 5;
#pragma unroll
    for (int j = 0; j < 4; j++)
        t[ty + 8 * j][tx] = W[(size_t)(k0 + ty + 8 * j) * N + n0 + tx];
    __syncthreads();
#pragma unroll
    for (int j = 0; j < 4; j++) {
        float v = t[tx][ty + 8 * j];
        __nv_bfloat16 h = __float2bfloat16(v);
        size_t idx = (size_t)(ro + n0 + ty + 8 * j) * Kd + k0 + tx;
        Thi[idx] = h;
        Tlo[idx] = __float2bfloat16(v - __bfloat162float(h));
    }
}

__global__ void prep_kernel(const float* __restrict__ hidden,
                            __nv_bfloat16* __restrict__ ahi, __nv_bfloat16* __restrict__ alo,
                            const float* __restrict__ Wq, const float* __restrict__ Wk,
                            const float* __restrict__ Wv,
                            __nv_bfloat16* __restrict__ bhi, __nv_bfloat16* __restrict__ blo)
{
    int b = blockIdx.x;
    if (b < 16384) { split_block(hidden, ahi, alo, b); return; }
    int tb = b - 16384;
    if (tb < 16384)      tsplit_block(Wq, bhi, blo, 4096, 0,    tb);
    else if (tb < 20480) tsplit_block(Wk, bhi, blo, 1024, 4096, tb - 16384);
    else                 tsplit_block(Wv, bhi, blo, 1024, 5120, tb - 20480);
}

__global__ void tsplit_kernel(const float* __restrict__ W, __nv_bfloat16* __restrict__ Thi,
                              __nv_bfloat16* __restrict__ Tlo)
{
    tsplit_block(W, Thi, Tlo, 4096, 0, blockIdx.x);
}

// ---------------------------------------------------------------------------
// bf16 mma.sync GEMM — EXACT R8 mainloop (unchanged, measured best).
// ---------------------------------------------------------------------------
constexpr int GSTAGE = 20480;
constexpr int GNSTG  = 4;
constexpr int GSMEM  = GNSTG * GSTAGE;

template <int MODE>
__global__ __launch_bounds__(256, 2)
void gemm_mma(const __nv_bfloat16* __restrict__ Ahi, const __nv_bfloat16* __restrict__ Alo,
              const __nv_bfloat16* __restrict__ Bhi, const __nv_bfloat16* __restrict__ Blo,
              const float* __restrict__ bq, const float* __restrict__ bk,
              const float* __restrict__ bv,
              float* __restrict__ Cq, float* __restrict__ Ck, float* __restrict__ Cv,
              int N)
{
    extern __shared__ __align__(16) char smc[];
    const uint32_t sbase = smem_u32(smc);
    const int tid = threadIdx.x;
    const int warp = tid >> 5, lane = tid & 31;
    const int m0 = blockIdx.y * 128, n0 = blockIdx.x * 128;
    constexpr int NKI = 3 * (Kd / 32);

    auto issue = [&](int kc) {
        const int buf = kc % GNSTG;
        const uint32_t sb = sbase + buf * GSTAGE;
        const int seg = kc >> 7;
        const int k0 = (kc & 127) * 32;
        const __nv_bfloat16* Aseg = (seg == 1) ? Alo : Ahi;
        const __nv_bfloat16* Bseg = (seg == 2) ? Blo : Bhi;
#pragma unroll
        for (int j = 0; j < 4; j++) {
            int task = tid + j * 256;
            if (task < 512) {
                int row = task >> 2, ch = task & 3;
                cp16(sb + row * 80 + ch * 16,
                     Aseg + (size_t)(m0 + row) * Kd + k0 + ch * 8);
            } else {
                int t2 = task - 512;
                int row = t2 >> 2, ch = t2 & 3;
                cp16(sb + 10240 + row * 80 + ch * 16,
                     Bseg + (size_t)(n0 + row) * Kd + k0 + ch * 8);
            }
        }
        asm volatile("cp.async.commit_group;" ::: "memory");
    };

    const int wm = (warp >> 1) * 32, wn = (warp & 1) * 64;

    uint32_t fa[2][2][4];
    uint32_t fb[2][4][4];

    auto ldfrags = [&](int buf) {
        const uint32_t sA = sbase + buf * GSTAGE;
        const uint32_t sB = sA + 10240;
#pragma unroll
        for (int ks = 0; ks < 2; ks++) {
            const int kb = ks * 32;
#pragma unroll
            for (int mi = 0; mi < 2; mi++)
                ldm4(fa[ks][mi], sA + (wm + mi * 16 + (lane & 15)) * 80 + kb + (lane >> 4) * 16);
#pragma unroll
            for (int nb = 0; nb < 4; nb++)
                ldm4(fb[ks][nb], sB + (wn + nb * 16 + ((lane >> 4) << 3) + (lane & 7)) * 80
                                   + kb + ((lane >> 3) & 1) * 16);
        }
    };

    float acc[2][8][4];
#pragma unroll
    for (int mi = 0; mi < 2; mi++)
#pragma unroll
        for (int ni = 0; ni < 8; ni++)
#pragma unroll
            for (int r = 0; r < 4; r++) acc[mi][ni][r] = 0.f;

    issue(0);
    issue(1);
    issue(2);
    asm volatile("cp.async.wait_group 2;" ::: "memory");
    __syncthreads();
    ldfrags(0);
    issue(3);

    for (int kc = 0; kc < NKI; kc++) {
#pragma unroll
        for (int ks = 0; ks < 2; ks++)
#pragma unroll
            for (int mi = 0; mi < 2; mi++)
#pragma unroll
                for (int ni = 0; ni < 8; ni++)
                    mma16816(acc[mi][ni], fa[ks][mi],
                             fb[ks][ni >> 1][2 * (ni & 1)], fb[ks][ni >> 1][2 * (ni & 1) + 1]);

        if (kc + 1 < NKI) {
            asm volatile("cp.async.wait_group 2;" ::: "memory");
            __syncthreads();
            ldfrags((kc + 1) % GNSTG);
            if (kc + 4 < NKI) issue(kc + 4);
        }
    }

#pragma unroll
    for (int mi = 0; mi < 2; mi++) {
#pragma unroll
        for (int rg = 0; rg < 2; rg++) {
            const int m = m0 + wm + mi * 16 + rg * 8 + (lane >> 2);
            const int bidx = m >> 11, sidx = m & 2047;
#pragma unroll
            for (int ni = 0; ni < 8; ni++) {
                const int col = n0 + wn + ni * 8 + (lane & 3) * 2;
                float v0 = acc[mi][ni][rg * 2 + 0];
                float v1 = acc[mi][ni][rg * 2 + 1];
                float* dst;
                if (MODE == 0) {
                    dst = Cq + (size_t)m * N + col;
                } else {
                    const float* bs;
                    float* base;
                    int c2, heads;
                    if (col < 4096)      { bs = bq; base = Cq; c2 = col;        heads = NHc; }
                    else if (col < 5120) { bs = bk; base = Ck; c2 = col - 4096; heads = NKVc; }
                    else                 { bs = bv; base = Cv; c2 = col - 5120; heads = NKVc; }
                    v0 += __ldg(bs + c2);
                    v1 += __ldg(bs + c2 + 1);
                    int h = c2 >> 7, d = c2 & 127;
                    dst = base + (((size_t)bidx * heads + h) * Sq + sidx) * HDc + d;
                }
                *reinterpret_cast<float2*>(dst) = make_float2(v0, v1);
            }
        }
    }
}

// ---------------------------------------------------------------------------
__global__ void rope2_kernel(float* __restrict__ q, float* __restrict__ k,
                             const float* __restrict__ cosp, const float* __restrict__ sinp)
{
    const int totQ = Bc * NHc * Sq * 64;
    const int totK = Bc * NKVc * Sq * 64;
    int i = blockIdx.x * blockDim.x + threadIdx.x;
    if (i >= totQ + totK) return;
    float* x;
    int heads;
    if (i < totQ) { x = q; heads = NHc; }
    else          { x = k; heads = NKVc; i -= totQ; }
    int dd = i & 63;
    int s = (i >> 6) & 2047;
    int bh = i >> 17;
    int h = bh % heads, b = bh / heads;
    size_t base = (((size_t)b * heads + h) * Sq + s) * HDc;
    size_t cbase = ((size_t)b * Sq + s) * HDc;
    float x1 = x[base + dd], x2 = x[base + dd + 64];
    float c1 = cosp[cbase + dd], c2 = cosp[cbase + dd + 64];
    float s1 = sinp[cbase + dd], s2 = sinp[cbase + dd + 64];
    x[base + dd]      = x1 * c1 - x2 * s1;
    x[base + dd + 64] = x2 * c2 + x1 * s2;
}

// ---------------------------------------------------------------------------
// Tensor-core flash attention, s-major fused passes (R15):
// per s-step the hi/lo fragments of each operand are loaded ONCE and all 3
// precision products issued together; P hi/lo conversion is inline per s
// (8 regs) instead of 128 regs held across the whole PV loop.
// grid (Sq/128, NH, B), 256 threads.
// ---------------------------------------------------------------------------
constexpr int FST = 136;
constexpr int FTILE = 128 * FST * 2;
constexpr int FL_SMEM = 6 * FTILE;  // 208896 B

__global__ __launch_bounds__(256, 1)
void flash_kernel(const float* __restrict__ Q, const float* __restrict__ Kg,
                  const float* __restrict__ Vg,
                  __nv_bfloat16* __restrict__ ahi, __nv_bfloat16* __restrict__ alo)
{
    extern __shared__ __align__(16) char fsm[];
    const uint32_t sb = smem_u32(fsm);
    const uint32_t sQhi = sb,             sQlo = sb + FTILE;
    const uint32_t sKhi = sb + 2 * FTILE, sKlo = sb + 3 * FTILE;
    const uint32_t sVhi = sb + 4 * FTILE, sVlo = sb + 5 * FTILE;

    const int tid = threadIdx.x;
    const int warp = tid >> 5, lane = tid & 31;
    const int b = blockIdx.z, h = blockIdx.y;
    const int kvh = h >> 2;
    const int q0 = blockIdx.x * 128;

    const float* qptr = Q  + (((size_t)b * NHc  + h)   * Sq + q0) * (size_t)HDc;
    const float* kptr = Kg + (((size_t)b * NKVc + kvh) * Sq) * (size_t)HDc;
    const float* vptr = Vg + (((size_t)b * NKVc + kvh) * Sq) * (size_t)HDc;

    auto cvst = [&](uint32_t bhi_, uint32_t blo_, int r, int c4, float4 v) {
        __nv_bfloat16 h0 = __float2bfloat16(v.x), h1 = __float2bfloat16(v.y);
        __nv_bfloat16 h2 = __float2bfloat16(v.z), h3 = __float2bfloat16(v.w);
        uint32_t off = (uint32_t)(r * FST + c4) * 2;
        *reinterpret_cast<__nv_bfloat162*>(fsm + (bhi_ - sb) + off)     = {h0, h1};
        *reinterpret_cast<__nv_bfloat162*>(fsm + (bhi_ - sb) + off + 4) = {h2, h3};
        *reinterpret_cast<__nv_bfloat162*>(fsm + (blo_ - sb) + off) =
            {__float2bfloat16(v.x - __bfloat162float(h0)),
             __float2bfloat16(v.y - __bfloat162float(h1))};
        *reinterpret_cast<__nv_bfloat162*>(fsm + (blo_ - sb) + off + 4) =
            {__float2bfloat16(v.z - __bfloat162float(h2)),
             __float2bfloat16(v.w - __bfloat162float(h3))};
    };

#pragma unroll
    for (int i = 0; i < 16; i++) {
        int idx = tid + i * 256;
        int r = idx >> 5, c4 = (idx & 31) * 4;
        cvst(sQhi, sQlo, r, c4, *reinterpret_cast<const float4*>(qptr + (size_t)r * HDc + c4));
    }

    float of[16][4];
#pragma unroll
    for (int ni = 0; ni < 16; ni++)
#pragma unroll
        for (int r = 0; r < 4; r++) of[ni][r] = 0.f;
    float mrow[2] = {-1e30f, -1e30f};
    float lrow[2] = {0.f, 0.f};

    const float scale = 0.08838834764831845f;

    const uint32_t aoff = (uint32_t)((16 * warp + (lane & 15)) * FST) * 2 + (lane >> 4) * 16;
    const uint32_t boff = (uint32_t)((((lane >> 4) << 3) + (lane & 7)) * FST) * 2
                        + ((lane >> 3) & 1) * 16;
    const uint32_t toff = (uint32_t)((((lane >> 3) & 1) * 8 + (lane & 7)) * FST) * 2
                        + (lane >> 4) * 16;

    for (int n0 = 0; n0 < Sq; n0 += 128) {
        __syncthreads();
#pragma unroll
        for (int i = 0; i < 16; i++) {
            int idx = tid + i * 256;
            int r = idx >> 5, c4 = (idx & 31) * 4;
            cvst(sKhi, sKlo, r, c4,
                 *reinterpret_cast<const float4*>(kptr + (size_t)(n0 + r) * HDc + c4));
            cvst(sVhi, sVlo, r, c4,
                 *reinterpret_cast<const float4*>(vptr + (size_t)(n0 + r) * HDc + c4));
        }
        __syncthreads();

        // ---- S = Q K^T, fused 3-precision, s-major ----
        float sf[16][4];
#pragma unroll
        for (int ni = 0; ni < 16; ni++)
#pragma unroll
            for (int r = 0; r < 4; r++) sf[ni][r] = 0.f;

#pragma unroll
        for (int s = 0; s < 8; s++) {
            uint32_t ah[4], al[4];
            ldm4(ah, sQhi + aoff + s * 32);
            ldm4(al, sQlo + aoff + s * 32);
#pragma unroll
            for (int nb = 0; nb < 8; nb++) {
                uint32_t bh[4], bl[4];
                uint32_t bo = boff + (uint32_t)(nb * 16 * FST) * 2 + s * 32;
                ldm4(bh, sKhi + bo);
                ldm4(bl, sKlo + bo);
                mma16816(sf[2 * nb],     ah, bh[0], bh[1]);
                mma16816(sf[2 * nb + 1], ah, bh[2], bh[3]);
                mma16816(sf[2 * nb],     al, bh[0], bh[1]);
                mma16816(sf[2 * nb + 1], al, bh[2], bh[3]);
                mma16816(sf[2 * nb],     ah, bl[0], bl[1]);
                mma16816(sf[2 * nb + 1], ah, bl[2], bl[3]);
            }
        }

        // ---- online softmax ----
        float corr[2];
#pragma unroll
        for (int half = 0; half < 2; half++) {
            float mt = -1e30f;
#pragma unroll
            for (int ni = 0; ni < 16; ni++)
                mt = fmaxf(mt, fmaxf(sf[ni][2 * half], sf[ni][2 * half + 1]));
            mt *= scale;
            mt = fmaxf(mt, __shfl_xor_sync(0xffffffffu, mt, 1));
            mt = fmaxf(mt, __shfl_xor_sync(0xffffffffu, mt, 2));
            float mnew = fmaxf(mrow[half], mt);
            corr[half] = __expf(mrow[half] - mnew);
            mrow[half] = mnew;
            float sum = 0.f;
#pragma unroll
            for (int ni = 0; ni < 16; ni++) {
                float p0 = __expf(sf[ni][2 * half]     * scale - mnew);
                float p1 = __expf(sf[ni][2 * half + 1] * scale - mnew);
                sf[ni][2 * half]     = p0;
                sf[ni][2 * half + 1] = p1;
                sum += p0 + p1;
            }
            sum += __shfl_xor_sync(0xffffffffu, sum, 1);
            sum += __shfl_xor_sync(0xffffffffu, sum, 2);
            lrow[half] = lrow[half] * corr[half] + sum;
        }

#pragma unroll
        for (int ni = 0; ni < 16; ni++) {
            of[ni][0] *= corr[0]; of[ni][1] *= corr[0];
            of[ni][2] *= corr[1]; of[ni][3] *= corr[1];
        }

        // ---- O += P V, fused 3-precision, s-major; P converted inline ----
#pragma unroll
        for (int s = 0; s < 8; s++) {
            uint32_t ph[4], pl[4];
#pragma unroll
            for (int q = 0; q < 4; q++) {
                int cell = 2 * s + (q >> 1);
                float p0 = sf[cell][(q & 1) * 2];
                float p1 = sf[cell][(q & 1) * 2 + 1];
                uint32_t hpk = packbf(p0, p1);
                __nv_bfloat162 hb = *reinterpret_cast<__nv_bfloat162*>(&hpk);
                ph[q] = hpk;
                pl[q] = packbf(p0 - __bfloat162float(hb.x),
                               p1 - __bfloat162float(hb.y));
            }
#pragma unroll
            for (int nb = 0; nb < 8; nb++) {
                uint32_t vh[4], vl[4];
                uint32_t vo = toff + (uint32_t)(16 * s * FST) * 2 + (uint32_t)(nb * 16) * 2;
                ldm4t(vh, sVhi + vo);
                ldm4t(vl, sVlo + vo);
                mma16816(of[2 * nb],     ph, vh[0], vh[1]);
                mma16816(of[2 * nb + 1], ph, vh[2], vh[3]);
                mma16816(of[2 * nb],     pl, vh[0], vh[1]);
                mma16816(of[2 * nb + 1], pl, vh[2], vh[3]);
                mma16816(of[2 * nb],     ph, vl[0], vl[1]);
                mma16816(of[2 * nb + 1], ph, vl[2], vl[3]);
            }
        }
    }

    // ---- epilogue: normalize + bf16 hi/lo split into A' ----
    float inv0 = 1.0f / lrow[0], inv1 = 1.0f / lrow[1];
    int r0 = q0 + 16 * warp + (lane >> 2);
    int r1 = r0 + 8;
    size_t arow0 = ((size_t)b * Sq + r0) * (size_t)HIDc + (size_t)h * HDc;
    size_t arow1 = ((size_t)b * Sq + r1) * (size_t)HIDc + (size_t)h * HDc;
#pragma unroll
    for (int ni = 0; ni < 16; ni++) {
        int d0 = 8 * ni + (lane & 3) * 2;
        {
            float v0 = of[ni][0] * inv0, v1 = of[ni][1] * inv0;
            uint32_t hp = packbf(v0, v1);
            __nv_bfloat162 hb = *reinterpret_cast<__nv_bfloat162*>(&hp);
            uint32_t lp = packbf(v0 - __bfloat162float(hb.x), v1 - __bfloat162float(hb.y));
            *reinterpret_cast<uint32_t*>(ahi + arow0 + d0) = hp;
            *reinterpret_cast<uint32_t*>(alo + arow0 + d0) = lp;
        }
        {
            float v0 = of[ni][2] * inv1, v1 = of[ni][3] * inv1;
            uint32_t hp = packbf(v0, v1);
            __nv_bfloat162 hb = *reinterpret_cast<__nv_bfloat162*>(&hp);
            uint32_t lp = packbf(v0 - __bfloat162float(hb.x), v1 - __bfloat162float(hb.y));
            *reinterpret_cast<uint32_t*>(ahi + arow1 + d0) = hp;
            *reinterpret_cast<uint32_t*>(alo + arow1 + d0) = lp;
        }
    }
}

// ---------------------------------------------------------------------------
extern "C" void kernel_launch(void* const* d_in, const int* in_sizes, int n_in,
                              void* d_out, int out_size)
{
    const float* hidden = (const float*)d_in[0];
    const float* cosp   = (const float*)d_in[1];
    const float* sinp   = (const float*)d_in[2];
    const float* Wq     = (const float*)d_in[3];
    const float* bq     = (const float*)d_in[4];
    const float* Wk     = (const float*)d_in[5];
    const float* bk     = (const float*)d_in[6];
    const float* Wv     = (const float*)d_in[7];
    const float* bv     = (const float*)d_in[8];
    const float* Wo     = (const float*)d_in[9];
    float* out = (float*)d_out;

    float *qb, *kb, *vb;
    __nv_bfloat16 *ahi, *alo, *bhi, *blo;
    cudaGetSymbolAddress((void**)&qb, g_Q);
    cudaGetSymbolAddress((void**)&kb, g_K);
    cudaGetSymbolAddress((void**)&vb, g_V);
    cudaGetSymbolAddress((void**)&ahi, g_Ahi);
    cudaGetSymbolAddress((void**)&alo, g_Alo);
    cudaGetSymbolAddress((void**)&bhi, g_Bhi);
    cudaGetSymbolAddress((void**)&blo, g_Blo);

    cudaFuncSetAttribute(gemm_mma<0>, cudaFuncAttributeMaxDynamicSharedMemorySize, GSMEM);
    cudaFuncSetAttribute(gemm_mma<1>, cudaFuncAttributeMaxDynamicSharedMemorySize, GSMEM);
    cudaFuncSetAttribute(flash_kernel, cudaFuncAttributeMaxDynamicSharedMemorySize, FL_SMEM);

    // 1. prep
    prep_kernel<<<16384 + 16384 + 4096 + 4096, 256>>>(hidden, ahi, alo, Wq, Wk, Wv, bhi, blo);

    // 2. fused QKV projection
    gemm_mma<1><<<dim3(NQKV / 128, 32), 256, GSMEM>>>(ahi, alo, bhi, blo,
                                                      bq, bk, bv, qb, kb, vb, NQKV);

    // 3. RoPE
    {
        int tot = Bc * NHc * Sq * 64 + Bc * NKVc * Sq * 64;
        rope2_kernel<<<(tot + 255) / 256, 256>>>(qb, kb, cosp, sinp);
    }

    // 4. tensor-core flash attention  <-- profiled
    flash_kernel<<<dim3(Sq / 128, NHc, Bc), 256, FL_SMEM>>>(qb, kb, vb, ahi, alo);

    // 5-6. output projection
    tsplit_kernel<<<16384, 256>>>(Wo, bhi, blo);
    gemm_mma<0><<<dim3(32, 32), 256, GSMEM>>>(ahi, alo, bhi, blo,
                                              nullptr, nullptr, nullptr,
                                              out, nullptr, nullptr, 4096);
}

// round 16
// speedup vs baseline: 1.5445x; 1.0047x over previous
#include <cuda_runtime.h>
#include <cuda_bf16.h>
#include <cstdint>
#include <cstddef>

constexpr int Bc = 2, Sq = 2048, HIDc = 4096, NHc = 32, NKVc = 8, HDc = 128;
constexpr int Kd = 4096;
constexpr int NQKV = 6144;

__device__ float g_Q[(size_t)Bc * NHc * Sq * HDc];
__device__ float g_K[(size_t)Bc * NKVc * Sq * HDc];
__device__ float g_V[(size_t)Bc * NKVc * Sq * HDc];
__device__ __nv_bfloat16 g_Ahi[(size_t)4096 * Kd];
__device__ __nv_bfloat16 g_Alo[(size_t)4096 * Kd];
__device__ __nv_bfloat16 g_Bhi[(size_t)NQKV * Kd];
__device__ __nv_bfloat16 g_Blo[(size_t)NQKV * Kd];

// ---------------------------------------------------------------------------
__device__ __forceinline__ uint32_t smem_u32(const void* p) {
    uint32_t a;
    asm("{ .reg .u64 t; cvta.to.shared.u64 t, %1; cvt.u32.u64 %0, t; }" : "=r"(a) : "l"(p));
    return a;
}
__device__ __forceinline__ void cp16(uint32_t d, const void* g) {
    asm volatile("cp.async.cg.shared.global [%0], [%1], 16;" :: "r"(d), "l"(g));
}
__device__ __forceinline__ void ldm4(uint32_t* r, uint32_t a) {
    asm volatile("ldmatrix.sync.aligned.m8n8.x4.shared.b16 {%0,%1,%2,%3}, [%4];"
        : "=r"(r[0]), "=r"(r[1]), "=r"(r[2]), "=r"(r[3]) : "r"(a));
}
__device__ __forceinline__ void ldm4t(uint32_t* r, uint32_t a) {
    asm volatile("ldmatrix.sync.aligned.m8n8.x4.trans.shared.b16 {%0,%1,%2,%3}, [%4];"
        : "=r"(r[0]), "=r"(r[1]), "=r"(r[2]), "=r"(r[3]) : "r"(a));
}
__device__ __forceinline__ void mma16816(float* c, const uint32_t* a, uint32_t b0, uint32_t b1) {
    asm volatile("mma.sync.aligned.m16n8k16.row.col.f32.bf16.bf16.f32 "
        "{%0,%1,%2,%3}, {%4,%5,%6,%7}, {%8,%9}, {%0,%1,%2,%3};"
        : "+f"(c[0]), "+f"(c[1]), "+f"(c[2]), "+f"(c[3])
        : "r"(a[0]), "r"(a[1]), "r"(a[2]), "r"(a[3]), "r"(b0), "r"(b1));
}
__device__ __forceinline__ uint32_t packbf(float lo, float hi) {
    uint32_t r;
    asm("cvt.rn.bf16x2.f32 %0, %1, %2;" : "=r"(r) : "f"(hi), "f"(lo));
    return r;
}

// ---------------------------------------------------------------------------
// split / transpose-split building blocks (unchanged)
// ---------------------------------------------------------------------------
__device__ __forceinline__ void split_block(const float* __restrict__ x,
                                            __nv_bfloat16* __restrict__ hi,
                                            __nv_bfloat16* __restrict__ lo,
                                            size_t blk)
{
    size_t i = blk * 1024 + (size_t)threadIdx.x * 4;
    float4 v = *reinterpret_cast<const float4*>(x + i);
    __nv_bfloat16 h0 = __float2bfloat16(v.x), h1 = __float2bfloat16(v.y);
    __nv_bfloat16 h2 = __float2bfloat16(v.z), h3 = __float2bfloat16(v.w);
    *reinterpret_cast<__nv_bfloat162*>(hi + i)     = {h0, h1};
    *reinterpret_cast<__nv_bfloat162*>(hi + i + 2) = {h2, h3};
    *reinterpret_cast<__nv_bfloat162*>(lo + i) =
        {__float2bfloat16(v.x - __bfloat162float(h0)),
         __float2bfloat16(v.y - __bfloat162float(h1))};
    *reinterpret_cast<__nv_bfloat162*>(lo + i + 2) =
        {__float2bfloat16(v.z - __bfloat162float(h2)),
         __float2bfloat16(v.w - __bfloat162float(h3))};
}

__device__ __forceinline__ void tsplit_block(const float* __restrict__ W,
                                             __nv_bfloat16* __restrict__ Thi,
                                             __nv_bfloat16* __restrict__ Tlo,
                                             int N, int ro, int tile)
{
    __shared__ float t[32][33];
    int nt = N / 32;
    int n0 = (tile % nt) * 32, k0 = (tile / nt) * 32;
    int tx = threadIdx.x & 31, ty = threadIdx.x >> 5;
#pragma unroll
    for (int j = 0; j < 4; j++)
        t[ty + 8 * j][tx] = W[(size_t)(k0 + ty + 8 * j) * N + n0 + tx];
    __syncthreads();
#pragma unroll
    for (int j = 0; j < 4; j++) {
        float v = t[tx][ty + 8 * j];
        __nv_bfloat16 h = __float2bfloat16(v);
        size_t idx = (size_t)(ro + n0 + ty + 8 * j) * Kd + k0 + tx;
        Thi[idx] = h;
        Tlo[idx] = __float2bfloat16(v - __bfloat162float(h));
    }
}

__global__ void prep_kernel(const float* __restrict__ hidden,
                            __nv_bfloat16* __restrict__ ahi, __nv_bfloat16* __restrict__ alo,
                            const float* __restrict__ Wq, const float* __restrict__ Wk,
                            const float* __restrict__ Wv,
                            __nv_bfloat16* __restrict__ bhi, __nv_bfloat16* __restrict__ blo)
{
    int b = blockIdx.x;
    if (b < 16384) { split_block(hidden, ahi, alo, b); return; }
    int tb = b - 16384;
    if (tb < 16384)      tsplit_block(Wq, bhi, blo, 4096, 0,    tb);
    else if (tb < 20480) tsplit_block(Wk, bhi, blo, 1024, 4096, tb - 16384);
    else                 tsplit_block(Wv, bhi, blo, 1024, 5120, tb - 20480);
}

__global__ void tsplit_kernel(const float* __restrict__ W, __nv_bfloat16* __restrict__ Thi,
                              __nv_bfloat16* __restrict__ Tlo)
{
    tsplit_block(W, Thi, Tlo, 4096, 0, blockIdx.x);
}

// ---------------------------------------------------------------------------
// bf16 mma.sync GEMM — EXACT R8 mainloop (unchanged, measured best).
// ---------------------------------------------------------------------------
constexpr int GSTAGE = 20480;
constexpr int GNSTG  = 4;
constexpr int GSMEM  = GNSTG * GSTAGE;

template <int MODE>
__global__ __launch_bounds__(256, 2)
void gemm_mma(const __nv_bfloat16* __restrict__ Ahi, const __nv_bfloat16* __restrict__ Alo,
              const __nv_bfloat16* __restrict__ Bhi, const __nv_bfloat16* __restrict__ Blo,
              const float* __restrict__ bq, const float* __restrict__ bk,
              const float* __restrict__ bv,
              float* __restrict__ Cq, float* __restrict__ Ck, float* __restrict__ Cv,
              int N)
{
    extern __shared__ __align__(16) char smc[];
    const uint32_t sbase = smem_u32(smc);
    const int tid = threadIdx.x;
    const int warp = tid >> 5, lane = tid & 31;
    const int m0 = blockIdx.y * 128, n0 = blockIdx.x * 128;
    constexpr int NKI = 3 * (Kd / 32);

    auto issue = [&](int kc) {
        const int buf = kc % GNSTG;
        const uint32_t sb = sbase + buf * GSTAGE;
        const int seg = kc >> 7;
        const int k0 = (kc & 127) * 32;
        const __nv_bfloat16* Aseg = (seg == 1) ? Alo : Ahi;
        const __nv_bfloat16* Bseg = (seg == 2) ? Blo : Bhi;
#pragma unroll
        for (int j = 0; j < 4; j++) {
            int task = tid + j * 256;
            if (task < 512) {
                int row = task >> 2, ch = task & 3;
                cp16(sb + row * 80 + ch * 16,
                     Aseg + (size_t)(m0 + row) * Kd + k0 + ch * 8);
            } else {
                int t2 = task - 512;
                int row = t2 >> 2, ch = t2 & 3;
                cp16(sb + 10240 + row * 80 + ch * 16,
                     Bseg + (size_t)(n0 + row) * Kd + k0 + ch * 8);
            }
        }
        asm volatile("cp.async.commit_group;" ::: "memory");
    };

    const int wm = (warp >> 1) * 32, wn = (warp & 1) * 64;

    uint32_t fa[2][2][4];
    uint32_t fb[2][4][4];

    auto ldfrags = [&](int buf) {
        const uint32_t sA = sbase + buf * GSTAGE;
        const uint32_t sB = sA + 10240;
#pragma unroll
        for (int ks = 0; ks < 2; ks++) {
            const int kb = ks * 32;
#pragma unroll
            for (int mi = 0; mi < 2; mi++)
                ldm4(fa[ks][mi], sA + (wm + mi * 16 + (lane & 15)) * 80 + kb + (lane >> 4) * 16);
#pragma unroll
            for (int nb = 0; nb < 4; nb++)
                ldm4(fb[ks][nb], sB + (wn + nb * 16 + ((lane >> 4) << 3) + (lane & 7)) * 80
                                   + kb + ((lane >> 3) & 1) * 16);
        }
    };

    float acc[2][8][4];
#pragma unroll
    for (int mi = 0; mi < 2; mi++)
#pragma unroll
        for (int ni = 0; ni < 8; ni++)
#pragma unroll
            for (int r = 0; r < 4; r++) acc[mi][ni][r] = 0.f;

    issue(0);
    issue(1);
    issue(2);
    asm volatile("cp.async.wait_group 2;" ::: "memory");
    __syncthreads();
    ldfrags(0);
    issue(3);

    for (int kc = 0; kc < NKI; kc++) {
#pragma unroll
        for (int ks = 0; ks < 2; ks++)
#pragma unroll
            for (int mi = 0; mi < 2; mi++)
#pragma unroll
                for (int ni = 0; ni < 8; ni++)
                    mma16816(acc[mi][ni], fa[ks][mi],
                             fb[ks][ni >> 1][2 * (ni & 1)], fb[ks][ni >> 1][2 * (ni & 1) + 1]);

        if (kc + 1 < NKI) {
            asm volatile("cp.async.wait_group 2;" ::: "memory");
            __syncthreads();
            ldfrags((kc + 1) % GNSTG);
            if (kc + 4 < NKI) issue(kc + 4);
        }
    }

#pragma unroll
    for (int mi = 0; mi < 2; mi++) {
#pragma unroll
        for (int rg = 0; rg < 2; rg++) {
            const int m = m0 + wm + mi * 16 + rg * 8 + (lane >> 2);
            const int bidx = m >> 11, sidx = m & 2047;
#pragma unroll
            for (int ni = 0; ni < 8; ni++) {
                const int col = n0 + wn + ni * 8 + (lane & 3) * 2;
                float v0 = acc[mi][ni][rg * 2 + 0];
                float v1 = acc[mi][ni][rg * 2 + 1];
                float* dst;
                if (MODE == 0) {
                    dst = Cq + (size_t)m * N + col;
                } else {
                    const float* bs;
                    float* base;
                    int c2, heads;
                    if (col < 4096)      { bs = bq; base = Cq; c2 = col;        heads = NHc; }
                    else if (col < 5120) { bs = bk; base = Ck; c2 = col - 4096; heads = NKVc; }
                    else                 { bs = bv; base = Cv; c2 = col - 5120; heads = NKVc; }
                    v0 += __ldg(bs + c2);
                    v1 += __ldg(bs + c2 + 1);
                    int h = c2 >> 7, d = c2 & 127;
                    dst = base + (((size_t)bidx * heads + h) * Sq + sidx) * HDc + d;
                }
                *reinterpret_cast<float2*>(dst) = make_float2(v0, v1);
            }
        }
    }
}

// ---------------------------------------------------------------------------
__global__ void rope2_kernel(float* __restrict__ q, float* __restrict__ k,
                             const float* __restrict__ cosp, const float* __restrict__ sinp)
{
    const int totQ = Bc * NHc * Sq * 64;
    const int totK = Bc * NKVc * Sq * 64;
    int i = blockIdx.x * blockDim.x + threadIdx.x;
    if (i >= totQ + totK) return;
    float* x;
    int heads;
    if (i < totQ) { x = q; heads = NHc; }
    else          { x = k; heads = NKVc; i -= totQ; }
    int dd = i & 63;
    int s = (i >> 6) & 2047;
    int bh = i >> 17;
    int h = bh % heads, b = bh / heads;
    size_t base = (((size_t)b * heads + h) * Sq + s) * HDc;
    size_t cbase = ((size_t)b * Sq + s) * HDc;
    float x1 = x[base + dd], x2 = x[base + dd + 64];
    float c1 = cosp[cbase + dd], c2 = cosp[cbase + dd + 64];
    float s1 = sinp[cbase + dd], s2 = sinp[cbase + dd + 64];
    x[base + dd]      = x1 * c1 - x2 * s1;
    x[base + dd + 64] = x2 * c2 + x1 * s2;
}

// ---------------------------------------------------------------------------
// Tensor-core flash attention, s-major fused passes (R15):
// per s-step the hi/lo fragments of each operand are loaded ONCE and all 3
// precision products issued together; P hi/lo conversion is inline per s
// (8 regs) instead of 128 regs held across the whole PV loop.
// grid (Sq/128, NH, B), 256 threads.
// ---------------------------------------------------------------------------
constexpr int FST = 136;
constexpr int FTILE = 128 * FST * 2;
constexpr int FL_SMEM = 6 * FTILE;  // 208896 B

__global__ __launch_bounds__(256, 1)
void flash_kernel(const float* __restrict__ Q, const float* __restrict__ Kg,
                  const float* __restrict__ Vg,
                  __nv_bfloat16* __restrict__ ahi, __nv_bfloat16* __restrict__ alo)
{
    extern __shared__ __align__(16) char fsm[];
    const uint32_t sb = smem_u32(fsm);
    const uint32_t sQhi = sb,             sQlo = sb + FTILE;
    const uint32_t sKhi = sb + 2 * FTILE, sKlo = sb + 3 * FTILE;
    const uint32_t sVhi = sb + 4 * FTILE, sVlo = sb + 5 * FTILE;

    const int tid = threadIdx.x;
    const int warp = tid >> 5, lane = tid & 31;
    const int b = blockIdx.z, h = blockIdx.y;
    const int kvh = h >> 2;
    const int q0 = blockIdx.x * 128;

    const float* qptr = Q  + (((size_t)b * NHc  + h)   * Sq + q0) * (size_t)HDc;
    const float* kptr = Kg + (((size_t)b * NKVc + kvh) * Sq) * (size_t)HDc;
    const float* vptr = Vg + (((size_t)b * NKVc + kvh) * Sq) * (size_t)HDc;

    auto cvst = [&](uint32_t bhi_, uint32_t blo_, int r, int c4, float4 v) {
        __nv_bfloat16 h0 = __float2bfloat16(v.x), h1 = __float2bfloat16(v.y);
        __nv_bfloat16 h2 = __float2bfloat16(v.z), h3 = __float2bfloat16(v.w);
        uint32_t off = (uint32_t)(r * FST + c4) * 2;
        *reinterpret_cast<__nv_bfloat162*>(fsm + (bhi_ - sb) + off)     = {h0, h1};
        *reinterpret_cast<__nv_bfloat162*>(fsm + (bhi_ - sb) + off + 4) = {h2, h3};
        *reinterpret_cast<__nv_bfloat162*>(fsm + (blo_ - sb) + off) =
            {__float2bfloat16(v.x - __bfloat162float(h0)),
             __float2bfloat16(v.y - __bfloat162float(h1))};
        *reinterpret_cast<__nv_bfloat162*>(fsm + (blo_ - sb) + off + 4) =
            {__float2bfloat16(v.z - __bfloat162float(h2)),
             __float2bfloat16(v.w - __bfloat162float(h3))};
    };

#pragma unroll
    for (int i = 0; i < 16; i++) {
        int idx = tid + i * 256;
        int r = idx >> 5, c4 = (idx & 31) * 4;
        cvst(sQhi, sQlo, r, c4, *reinterpret_cast<const float4*>(qptr + (size_t)r * HDc + c4));
    }

    float of[16][4];
#pragma unroll
    for (int ni = 0; ni < 16; ni++)
#pragma unroll
        for (int r = 0; r < 4; r++) of[ni][r] = 0.f;
    float mrow[2] = {-1e30f, -1e30f};
    float lrow[2] = {0.f, 0.f};

    const float scale = 0.08838834764831845f;

    const uint32_t aoff = (uint32_t)((16 * warp + (lane & 15)) * FST) * 2 + (lane >> 4) * 16;
    const uint32_t boff = (uint32_t)((((lane >> 4) << 3) + (lane & 7)) * FST) * 2
                        + ((lane >> 3) & 1) * 16;
    const uint32_t toff = (uint32_t)((((lane >> 3) & 1) * 8 + (lane & 7)) * FST) * 2
                        + (lane >> 4) * 16;

    for (int n0 = 0; n0 < Sq; n0 += 128) {
        __syncthreads();
#pragma unroll
        for (int i = 0; i < 16; i++) {
            int idx = tid + i * 256;
            int r = idx >> 5, c4 = (idx & 31) * 4;
            cvst(sKhi, sKlo, r, c4,
                 *reinterpret_cast<const float4*>(kptr + (size_t)(n0 + r) * HDc + c4));
            cvst(sVhi, sVlo, r, c4,
                 *reinterpret_cast<const float4*>(vptr + (size_t)(n0 + r) * HDc + c4));
        }
        __syncthreads();

        // ---- S = Q K^T, fused 3-precision, s-major ----
        float sf[16][4];
#pragma unroll
        for (int ni = 0; ni < 16; ni++)
#pragma unroll
            for (int r = 0; r < 4; r++) sf[ni][r] = 0.f;

#pragma unroll
        for (int s = 0; s < 8; s++) {
            uint32_t ah[4], al[4];
            ldm4(ah, sQhi + aoff + s * 32);
            ldm4(al, sQlo + aoff + s * 32);
#pragma unroll
            for (int nb = 0; nb < 8; nb++) {
                uint32_t bh[4], bl[4];
                uint32_t bo = boff + (uint32_t)(nb * 16 * FST) * 2 + s * 32;
                ldm4(bh, sKhi + bo);
                ldm4(bl, sKlo + bo);
                mma16816(sf[2 * nb],     ah, bh[0], bh[1]);
                mma16816(sf[2 * nb + 1], ah, bh[2], bh[3]);
                mma16816(sf[2 * nb],     al, bh[0], bh[1]);
                mma16816(sf[2 * nb + 1], al, bh[2], bh[3]);
                mma16816(sf[2 * nb],     ah, bl[0], bl[1]);
                mma16816(sf[2 * nb + 1], ah, bl[2], bl[3]);
            }
        }

        // ---- online softmax ----
        float corr[2];
#pragma unroll
        for (int half = 0; half < 2; half++) {
            float mt = -1e30f;
#pragma unroll
            for (int ni = 0; ni < 16; ni++)
                mt = fmaxf(mt, fmaxf(sf[ni][2 * half], sf[ni][2 * half + 1]));
            mt *= scale;
            mt = fmaxf(mt, __shfl_xor_sync(0xffffffffu, mt, 1));
            mt = fmaxf(mt, __shfl_xor_sync(0xffffffffu, mt, 2));
            float mnew = fmaxf(mrow[half], mt);
            corr[half] = __expf(mrow[half] - mnew);
            mrow[half] = mnew;
            float sum = 0.f;
#pragma unroll
            for (int ni = 0; ni < 16; ni++) {
                float p0 = __expf(sf[ni][2 * half]     * scale - mnew);
                float p1 = __expf(sf[ni][2 * half + 1] * scale - mnew);
                sf[ni][2 * half]     = p0;
                sf[ni][2 * half + 1] = p1;
                sum += p0 + p1;
            }
            sum += __shfl_xor_sync(0xffffffffu, sum, 1);
            sum += __shfl_xor_sync(0xffffffffu, sum, 2);
            lrow[half] = lrow[half] * corr[half] + sum;
        }

#pragma unroll
        for (int ni = 0; ni < 16; ni++) {
            of[ni][0] *= corr[0]; of[ni][1] *= corr[0];
            of[ni][2] *= corr[1]; of[ni][3] *= corr[1];
        }

        // ---- O += P V, fused 3-precision, s-major; P converted inline ----
#pragma unroll
        for (int s = 0; s < 8; s++) {
            uint32_t ph[4], pl[4];
#pragma unroll
            for (int q = 0; q < 4; q++) {
                int cell = 2 * s + (q >> 1);
                float p0 = sf[cell][(q & 1) * 2];
                float p1 = sf[cell][(q & 1) * 2 + 1];
                uint32_t hpk = packbf(p0, p1);
                __nv_bfloat162 hb = *reinterpret_cast<__nv_bfloat162*>(&hpk);
                ph[q] = hpk;
                pl[q] = packbf(p0 - __bfloat162float(hb.x),
                               p1 - __bfloat162float(hb.y));
            }
#pragma unroll
            for (int nb = 0; nb < 8; nb++) {
                uint32_t vh[4], vl[4];
                uint32_t vo = toff + (uint32_t)(16 * s * FST) * 2 + (uint32_t)(nb * 16) * 2;
                ldm4t(vh, sVhi + vo);
                ldm4t(vl, sVlo + vo);
                mma16816(of[2 * nb],     ph, vh[0], vh[1]);
                mma16816(of[2 * nb + 1], ph, vh[2], vh[3]);
                mma16816(of[2 * nb],     pl, vh[0], vh[1]);
                mma16816(of[2 * nb + 1], pl, vh[2], vh[3]);
                mma16816(of[2 * nb],     ph, vl[0], vl[1]);
                mma16816(of[2 * nb + 1], ph, vl[2], vl[3]);
            }
        }
    }

    // ---- epilogue: normalize + bf16 hi/lo split into A' ----
    float inv0 = 1.0f / lrow[0], inv1 = 1.0f / lrow[1];
    int r0 = q0 + 16 * warp + (lane >> 2);
    int r1 = r0 + 8;
    size_t arow0 = ((size_t)b * Sq + r0) * (size_t)HIDc + (size_t)h * HDc;
    size_t arow1 = ((size_t)b * Sq + r1) * (size_t)HIDc + (size_t)h * HDc;
#pragma unroll
    for (int ni = 0; ni < 16; ni++) {
        int d0 = 8 * ni + (lane & 3) * 2;
        {
            float v0 = of[ni][0] * inv0, v1 = of[ni][1] * inv0;
            uint32_t hp = packbf(v0, v1);
            __nv_bfloat162 hb = *reinterpret_cast<__nv_bfloat162*>(&hp);
            uint32_t lp = packbf(v0 - __bfloat162float(hb.x), v1 - __bfloat162float(hb.y));
            *reinterpret_cast<uint32_t*>(ahi + arow0 + d0) = hp;
            *reinterpret_cast<uint32_t*>(alo + arow0 + d0) = lp;
        }
        {
            float v0 = of[ni][2] * inv1, v1 = of[ni][3] * inv1;
            uint32_t hp = packbf(v0, v1);
            __nv_bfloat162 hb = *reinterpret_cast<__nv_bfloat162*>(&hp);
            uint32_t lp = packbf(v0 - __bfloat162float(hb.x), v1 - __bfloat162float(hb.y));
            *reinterpret_cast<uint32_t*>(ahi + arow1 + d0) = hp;
            *reinterpret_cast<uint32_t*>(alo + arow1 + d0) = lp;
        }
    }
}

// ---------------------------------------------------------------------------
extern "C" void kernel_launch(void* const* d_in, const int* in_sizes, int n_in,
                              void* d_out, int out_size)
{
    const float* hidden = (const float*)d_in[0];
    const float* cosp   = (const float*)d_in[1];
    const float* sinp   = (const float*)d_in[2];
    const float* Wq     = (const float*)d_in[3];
    const float* bq     = (const float*)d_in[4];
    const float* Wk     = (const float*)d_in[5];
    const float* bk     = (const float*)d_in[6];
    const float* Wv     = (const float*)d_in[7];
    const float* bv     = (const float*)d_in[8];
    const float* Wo     = (const float*)d_in[9];
    float* out = (float*)d_out;

    float *qb, *kb, *vb;
    __nv_bfloat16 *ahi, *alo, *bhi, *blo;
    cudaGetSymbolAddress((void**)&qb, g_Q);
    cudaGetSymbolAddress((void**)&kb, g_K);
    cudaGetSymbolAddress((void**)&vb, g_V);
    cudaGetSymbolAddress((void**)&ahi, g_Ahi);
    cudaGetSymbolAddress((void**)&alo, g_Alo);
    cudaGetSymbolAddress((void**)&bhi, g_Bhi);
    cudaGetSymbolAddress((void**)&blo, g_Blo);

    cudaFuncSetAttribute(gemm_mma<0>, cudaFuncAttributeMaxDynamicSharedMemorySize, GSMEM);
    cudaFuncSetAttribute(gemm_mma<1>, cudaFuncAttributeMaxDynamicSharedMemorySize, GSMEM);
    cudaFuncSetAttribute(flash_kernel, cudaFuncAttributeMaxDynamicSharedMemorySize, FL_SMEM);

    // 1. prep
    prep_kernel<<<16384 + 16384 + 4096 + 4096, 256>>>(hidden, ahi, alo, Wq, Wk, Wv, bhi, blo);

    // 2. fused QKV projection
    gemm_mma<1><<<dim3(NQKV / 128, 32), 256, GSMEM>>>(ahi, alo, bhi, blo,
                                                      bq, bk, bv, qb, kb, vb, NQKV);

    // 3. RoPE
    {
        int tot = Bc * NHc * Sq * 64 + Bc * NKVc * Sq * 64;
        rope2_kernel<<<(tot + 255) / 256, 256>>>(qb, kb, cosp, sinp);
    }

    // 4. tensor-core flash attention  <-- profiled
    flash_kernel<<<dim3(Sq / 128, NHc, Bc), 256, FL_SMEM>>>(qb, kb, vb, ahi, alo);

    // 5-6. output projection
    tsplit_kernel<<<16384, 256>>>(Wo, bhi, blo);
    gemm_mma<0><<<dim3(32, 32), 256, GSMEM>>>(ahi, alo, bhi, blo,
                                              nullptr, nullptr, nullptr,
                                              out, nullptr, nullptr, 4096);
}

// round 17
// speedup vs baseline: 1.5680x; 1.0153x over previous
#include <cuda_runtime.h>
#include <cuda_bf16.h>
#include <cstdint>
#include <cstddef>

constexpr int Bc = 2, Sq = 2048, HIDc = 4096, NHc = 32, NKVc = 8, HDc = 128;
constexpr int Kd = 4096;
constexpr int NQKV = 6144;

__device__ float g_Q[(size_t)Bc * NHc * Sq * HDc];
__device__ float g_K[(size_t)Bc * NKVc * Sq * HDc];
__device__ float g_V[(size_t)Bc * NKVc * Sq * HDc];
__device__ __nv_bfloat16 g_Ahi[(size_t)4096 * Kd];
__device__ __nv_bfloat16 g_Alo[(size_t)4096 * Kd];
__device__ __nv_bfloat16 g_Bhi[(size_t)NQKV * Kd];
__device__ __nv_bfloat16 g_Blo[(size_t)NQKV * Kd];

// ---------------------------------------------------------------------------
__device__ __forceinline__ uint32_t smem_u32(const void* p) {
    uint32_t a;
    asm("{ .reg .u64 t; cvta.to.shared.u64 t, %1; cvt.u32.u64 %0, t; }" : "=r"(a) : "l"(p));
    return a;
}
__device__ __forceinline__ void cp16(uint32_t d, const void* g) {
    asm volatile("cp.async.cg.shared.global [%0], [%1], 16;" :: "r"(d), "l"(g));
}
__device__ __forceinline__ void ldm4(uint32_t* r, uint32_t a) {
    asm volatile("ldmatrix.sync.aligned.m8n8.x4.shared.b16 {%0,%1,%2,%3}, [%4];"
        : "=r"(r[0]), "=r"(r[1]), "=r"(r[2]), "=r"(r[3]) : "r"(a));
}
__device__ __forceinline__ void ldm4t(uint32_t* r, uint32_t a) {
    asm volatile("ldmatrix.sync.aligned.m8n8.x4.trans.shared.b16 {%0,%1,%2,%3}, [%4];"
        : "=r"(r[0]), "=r"(r[1]), "=r"(r[2]), "=r"(r[3]) : "r"(a));
}
__device__ __forceinline__ void mma16816(float* c, const uint32_t* a, uint32_t b0, uint32_t b1) {
    asm volatile("mma.sync.aligned.m16n8k16.row.col.f32.bf16.bf16.f32 "
        "{%0,%1,%2,%3}, {%4,%5,%6,%7}, {%8,%9}, {%0,%1,%2,%3};"
        : "+f"(c[0]), "+f"(c[1]), "+f"(c[2]), "+f"(c[3])
        : "r"(a[0]), "r"(a[1]), "r"(a[2]), "r"(a[3]), "r"(b0), "r"(b1));
}
__device__ __forceinline__ uint32_t packbf(float lo, float hi) {
    uint32_t r;
    asm("cvt.rn.bf16x2.f32 %0, %1, %2;" : "=r"(r) : "f"(hi), "f"(lo));
    return r;
}

// ---------------------------------------------------------------------------
// split / transpose-split building blocks (unchanged)
// ---------------------------------------------------------------------------
__device__ __forceinline__ void split_block(const float* __restrict__ x,
                                            __nv_bfloat16* __restrict__ hi,
                                            __nv_bfloat16* __restrict__ lo,
                                            size_t blk)
{
    size_t i = blk * 1024 + (size_t)threadIdx.x * 4;
    float4 v = *reinterpret_cast<const float4*>(x + i);
    __nv_bfloat16 h0 = __float2bfloat16(v.x), h1 = __float2bfloat16(v.y);
    __nv_bfloat16 h2 = __float2bfloat16(v.z), h3 = __float2bfloat16(v.w);
    *reinterpret_cast<__nv_bfloat162*>(hi + i)     = {h0, h1};
    *reinterpret_cast<__nv_bfloat162*>(hi + i + 2) = {h2, h3};
    *reinterpret_cast<__nv_bfloat162*>(lo + i) =
        {__float2bfloat16(v.x - __bfloat162float(h0)),
         __float2bfloat16(v.y - __bfloat162float(h1))};
    *reinterpret_cast<__nv_bfloat162*>(lo + i + 2) =
        {__float2bfloat16(v.z - __bfloat162float(h2)),
         __float2bfloat16(v.w - __bfloat162float(h3))};
}

__device__ __forceinline__ void tsplit_block(const float* __restrict__ W,
                                             __nv_bfloat16* __restrict__ Thi,
                                             __nv_bfloat16* __restrict__ Tlo,
                                             int N, int ro, int tile)
{
    __shared__ float t[32][33];
    int nt = N / 32;
    int n0 = (tile % nt) * 32, k0 = (tile / nt) * 32;
    int tx = threadIdx.x & 31, ty = threadIdx.x >> 5;
#pragma unroll
    for (int j = 0; j < 4; j++)
        t[ty + 8 * j][tx] = W[(size_t)(k0 + ty + 8 * j) * N + n0 + tx];
    __syncthreads();
#pragma unroll
    for (int j = 0; j < 4; j++) {
        float v = t[tx][ty + 8 * j];
        __nv_bfloat16 h = __float2bfloat16(v);
        size_t idx = (size_t)(ro + n0 + ty + 8 * j) * Kd + k0 + tx;
        Thi[idx] = h;
        Tlo[idx] = __float2bfloat16(v - __bfloat162float(h));
    }
}

__global__ void prep_kernel(const float* __restrict__ hidden,
                            __nv_bfloat16* __restrict__ ahi, __nv_bfloat16* __restrict__ alo,
                            const float* __restrict__ Wq, const float* __restrict__ Wk,
                            const float* __restrict__ Wv,
                            __nv_bfloat16* __restrict__ bhi, __nv_bfloat16* __restrict__ blo)
{
    int b = blockIdx.x;
    if (b < 16384) { split_block(hidden, ahi, alo, b); return; }
    int tb = b - 16384;
    if (tb < 16384)      tsplit_block(Wq, bhi, blo, 4096, 0,    tb);
    else if (tb < 20480) tsplit_block(Wk, bhi, blo, 1024, 4096, tb - 16384);
    else                 tsplit_block(Wv, bhi, blo, 1024, 5120, tb - 20480);
}

__global__ void tsplit_kernel(const float* __restrict__ W, __nv_bfloat16* __restrict__ Thi,
                              __nv_bfloat16* __restrict__ Tlo)
{
    tsplit_block(W, Thi, Tlo, 4096, 0, blockIdx.x);
}

// ---------------------------------------------------------------------------
// bf16 mma.sync GEMM over virtual K' = 3*4096 — BK=64 chunks (R17):
// one barrier per 64 MMAs (192 barriers, was 384). Sub-step 1 of each chunk
// needs no barrier (published by the previous chunk's barrier). Same frag
// register layout as the measured-best R8 loop. 3 stages x 36.9 KB.
// MODE 0: row-major C (N=4096), no bias.
// MODE 1: fused QKV epilogue (N=6144): col<4096 -> Q, <5120 -> K, else V.
// ---------------------------------------------------------------------------
constexpr int GROWB  = 144;                 // bytes per SMEM row (128 data + 16 pad)
constexpr int GSTAGE = 2 * 128 * GROWB;     // 36864: A tile + B tile
constexpr int GNSTG  = 3;
constexpr int GSMEM  = GNSTG * GSTAGE;      // 110592

template <int MODE>
__global__ __launch_bounds__(256, 2)
void gemm_mma(const __nv_bfloat16* __restrict__ Ahi, const __nv_bfloat16* __restrict__ Alo,
              const __nv_bfloat16* __restrict__ Bhi, const __nv_bfloat16* __restrict__ Blo,
              const float* __restrict__ bq, const float* __restrict__ bk,
              const float* __restrict__ bv,
              float* __restrict__ Cq, float* __restrict__ Ck, float* __restrict__ Cv,
              int N)
{
    extern __shared__ __align__(16) char smc[];
    const uint32_t sbase = smem_u32(smc);
    const int tid = threadIdx.x;
    const int warp = tid >> 5, lane = tid & 31;
    const int m0 = blockIdx.y * 128, n0 = blockIdx.x * 128;
    constexpr int NKI = 3 * (Kd / 64);      // 192 chunks of 64 k

    auto issue = [&](int kc) {
        const int buf = kc % GNSTG;
        const uint32_t sb = sbase + buf * GSTAGE;
        const int seg = kc >> 6;            // 64 chunks per segment
        const int k0 = (kc & 63) * 64;
        const __nv_bfloat16* Aseg = (seg == 1) ? Alo : Ahi;
        const __nv_bfloat16* Bseg = (seg == 2) ? Blo : Bhi;
#pragma unroll
        for (int j = 0; j < 8; j++) {
            int task = tid + j * 256;
            if (task < 1024) {
                int row = task >> 3, ch = task & 7;
                cp16(sb + row * GROWB + ch * 16,
                     Aseg + (size_t)(m0 + row) * Kd + k0 + ch * 8);
            } else {
                int t2 = task - 1024;
                int row = t2 >> 3, ch = t2 & 7;
                cp16(sb + 128 * GROWB + row * GROWB + ch * 16,
                     Bseg + (size_t)(n0 + row) * Kd + k0 + ch * 8);
            }
        }
        asm volatile("cp.async.commit_group;" ::: "memory");
    };

    const int wm = (warp >> 1) * 32, wn = (warp & 1) * 64;

    uint32_t fa[2][2][4];
    uint32_t fb[2][4][4];

    // load fragments for 32-k sub-step `sub` (0 or 1) of chunk in buffer `buf`
    auto ldfrags = [&](int buf, int sub) {
        const uint32_t sA = sbase + buf * GSTAGE + sub * 64;
        const uint32_t sB = sA + 128 * GROWB;
#pragma unroll
        for (int ks = 0; ks < 2; ks++) {
            const int kb = ks * 32;
#pragma unroll
            for (int mi = 0; mi < 2; mi++)
                ldm4(fa[ks][mi], sA + (wm + mi * 16 + (lane & 15)) * GROWB + kb + (lane >> 4) * 16);
#pragma unroll
            for (int nb = 0; nb < 4; nb++)
                ldm4(fb[ks][nb], sB + (wn + nb * 16 + ((lane >> 4) << 3) + (lane & 7)) * GROWB
                                   + kb + ((lane >> 3) & 1) * 16);
        }
    };

    float acc[2][8][4];
#pragma unroll
    for (int mi = 0; mi < 2; mi++)
#pragma unroll
        for (int ni = 0; ni < 8; ni++)
#pragma unroll
            for (int r = 0; r < 4; r++) acc[mi][ni][r] = 0.f;

    auto mmablock = [&]() {
#pragma unroll
        for (int ks = 0; ks < 2; ks++)
#pragma unroll
            for (int mi = 0; mi < 2; mi++)
#pragma unroll
                for (int ni = 0; ni < 8; ni++)
                    mma16816(acc[mi][ni], fa[ks][mi],
                             fb[ks][ni >> 1][2 * (ni & 1)], fb[ks][ni >> 1][2 * (ni & 1) + 1]);
    };

    issue(0);
    issue(1);
    issue(2);
    asm volatile("cp.async.wait_group 2;" ::: "memory");  // chunk 0 complete
    __syncthreads();
    ldfrags(0, 0);

    for (int kc = 0; kc < NKI; kc++) {
        mmablock();                  // sub 0 (frags held)
        ldfrags(kc % GNSTG, 1);      // sub 1: same chunk, already published
        mmablock();                  // sub 1
        if (kc + 1 < NKI) {
            asm volatile("cp.async.wait_group 1;" ::: "memory");  // chunk kc+1 done
            __syncthreads();         // publish kc+1; buffer kc free
            ldfrags((kc + 1) % GNSTG, 0);
            if (kc + 3 < NKI) issue(kc + 3);
        }
    }

    // Epilogue
#pragma unroll
    for (int mi = 0; mi < 2; mi++) {
#pragma unroll
        for (int rg = 0; rg < 2; rg++) {
            const int m = m0 + wm + mi * 16 + rg * 8 + (lane >> 2);
            const int bidx = m >> 11, sidx = m & 2047;
#pragma unroll
            for (int ni = 0; ni < 8; ni++) {
                const int col = n0 + wn + ni * 8 + (lane & 3) * 2;
                float v0 = acc[mi][ni][rg * 2 + 0];
                float v1 = acc[mi][ni][rg * 2 + 1];
                float* dst;
                if (MODE == 0) {
                    dst = Cq + (size_t)m * N + col;
                } else {
                    const float* bs;
                    float* base;
                    int c2, heads;
                    if (col < 4096)      { bs = bq; base = Cq; c2 = col;        heads = NHc; }
                    else if (col < 5120) { bs = bk; base = Ck; c2 = col - 4096; heads = NKVc; }
                    else                 { bs = bv; base = Cv; c2 = col - 5120; heads = NKVc; }
                    v0 += __ldg(bs + c2);
                    v1 += __ldg(bs + c2 + 1);
                    int h = c2 >> 7, d = c2 & 127;
                    dst = base + (((size_t)bidx * heads + h) * Sq + sidx) * HDc + d;
                }
                *reinterpret_cast<float2*>(dst) = make_float2(v0, v1);
            }
        }
    }
}

// ---------------------------------------------------------------------------
__global__ void rope2_kernel(float* __restrict__ q, float* __restrict__ k,
                             const float* __restrict__ cosp, const float* __restrict__ sinp)
{
    const int totQ = Bc * NHc * Sq * 64;
    const int totK = Bc * NKVc * Sq * 64;
    int i = blockIdx.x * blockDim.x + threadIdx.x;
    if (i >= totQ + totK) return;
    float* x;
    int heads;
    if (i < totQ) { x = q; heads = NHc; }
    else          { x = k; heads = NKVc; i -= totQ; }
    int dd = i & 63;
    int s = (i >> 6) & 2047;
    int bh = i >> 17;
    int h = bh % heads, b = bh / heads;
    size_t base = (((size_t)b * heads + h) * Sq + s) * HDc;
    size_t cbase = ((size_t)b * Sq + s) * HDc;
    float x1 = x[base + dd], x2 = x[base + dd + 64];
    float c1 = cosp[cbase + dd], c2 = cosp[cbase + dd + 64];
    float s1 = sinp[cbase + dd], s2 = sinp[cbase + dd + 64];
    x[base + dd]      = x1 * c1 - x2 * s1;
    x[base + dd + 64] = x2 * c2 + x1 * s2;
}

// ---------------------------------------------------------------------------
// Tensor-core flash attention, s-major fused passes (R15 — measured best).
// grid (Sq/128, NH, B), 256 threads.
// ---------------------------------------------------------------------------
constexpr int FST = 136;
constexpr int FTILE = 128 * FST * 2;
constexpr int FL_SMEM = 6 * FTILE;  // 208896 B

__global__ __launch_bounds__(256, 1)
void flash_kernel(const float* __restrict__ Q, const float* __restrict__ Kg,
                  const float* __restrict__ Vg,
                  __nv_bfloat16* __restrict__ ahi, __nv_bfloat16* __restrict__ alo)
{
    extern __shared__ __align__(16) char fsm[];
    const uint32_t sb = smem_u32(fsm);
    const uint32_t sQhi = sb,             sQlo = sb + FTILE;
    const uint32_t sKhi = sb + 2 * FTILE, sKlo = sb + 3 * FTILE;
    const uint32_t sVhi = sb + 4 * FTILE, sVlo = sb + 5 * FTILE;

    const int tid = threadIdx.x;
    const int warp = tid >> 5, lane = tid & 31;
    const int b = blockIdx.z, h = blockIdx.y;
    const int kvh = h >> 2;
    const int q0 = blockIdx.x * 128;

    const float* qptr = Q  + (((size_t)b * NHc  + h)   * Sq + q0) * (size_t)HDc;
    const float* kptr = Kg + (((size_t)b * NKVc + kvh) * Sq) * (size_t)HDc;
    const float* vptr = Vg + (((size_t)b * NKVc + kvh) * Sq) * (size_t)HDc;

    auto cvst = [&](uint32_t bhi_, uint32_t blo_, int r, int c4, float4 v) {
        __nv_bfloat16 h0 = __float2bfloat16(v.x), h1 = __float2bfloat16(v.y);
        __nv_bfloat16 h2 = __float2bfloat16(v.z), h3 = __float2bfloat16(v.w);
        uint32_t off = (uint32_t)(r * FST + c4) * 2;
        *reinterpret_cast<__nv_bfloat162*>(fsm + (bhi_ - sb) + off)     = {h0, h1};
        *reinterpret_cast<__nv_bfloat162*>(fsm + (bhi_ - sb) + off + 4) = {h2, h3};
        *reinterpret_cast<__nv_bfloat162*>(fsm + (blo_ - sb) + off) =
            {__float2bfloat16(v.x - __bfloat162float(h0)),
             __float2bfloat16(v.y - __bfloat162float(h1))};
        *reinterpret_cast<__nv_bfloat162*>(fsm + (blo_ - sb) + off + 4) =
            {__float2bfloat16(v.z - __bfloat162float(h2)),
             __float2bfloat16(v.w - __bfloat162float(h3))};
    };

#pragma unroll
    for (int i = 0; i < 16; i++) {
        int idx = tid + i * 256;
        int r = idx >> 5, c4 = (idx & 31) * 4;
        cvst(sQhi, sQlo, r, c4, *reinterpret_cast<const float4*>(qptr + (size_t)r * HDc + c4));
    }

    float of[16][4];
#pragma unroll
    for (int ni = 0; ni < 16; ni++)
#pragma unroll
        for (int r = 0; r < 4; r++) of[ni][r] = 0.f;
    float mrow[2] = {-1e30f, -1e30f};
    float lrow[2] = {0.f, 0.f};

    const float scale = 0.08838834764831845f;

    const uint32_t aoff = (uint32_t)((16 * warp + (lane & 15)) * FST) * 2 + (lane >> 4) * 16;
    const uint32_t boff = (uint32_t)((((lane >> 4) << 3) + (lane & 7)) * FST) * 2
                        + ((lane >> 3) & 1) * 16;
    const uint32_t toff = (uint32_t)((((lane >> 3) & 1) * 8 + (lane & 7)) * FST) * 2
                        + (lane >> 4) * 16;

    for (int n0 = 0; n0 < Sq; n0 += 128) {
        __syncthreads();
#pragma unroll
        for (int i = 0; i < 16; i++) {
            int idx = tid + i * 256;
            int r = idx >> 5, c4 = (idx & 31) * 4;
            cvst(sKhi, sKlo, r, c4,
                 *reinterpret_cast<const float4*>(kptr + (size_t)(n0 + r) * HDc + c4));
            cvst(sVhi, sVlo, r, c4,
                 *reinterpret_cast<const float4*>(vptr + (size_t)(n0 + r) * HDc + c4));
        }
        __syncthreads();

        float sf[16][4];
#pragma unroll
        for (int ni = 0; ni < 16; ni++)
#pragma unroll
            for (int r = 0; r < 4; r++) sf[ni][r] = 0.f;

#pragma unroll
        for (int s = 0; s < 8; s++) {
            uint32_t ah[4], al[4];
            ldm4(ah, sQhi + aoff + s * 32);
            ldm4(al, sQlo + aoff + s * 32);
#pragma unroll
            for (int nb = 0; nb < 8; nb++) {
                uint32_t bh[4], bl[4];
                uint32_t bo = boff + (uint32_t)(nb * 16 * FST) * 2 + s * 32;
                ldm4(bh, sKhi + bo);
                ldm4(bl, sKlo + bo);
                mma16816(sf[2 * nb],     ah, bh[0], bh[1]);
                mma16816(sf[2 * nb + 1], ah, bh[2], bh[3]);
                mma16816(sf[2 * nb],     al, bh[0], bh[1]);
                mma16816(sf[2 * nb + 1], al, bh[2], bh[3]);
                mma16816(sf[2 * nb],     ah, bl[0], bl[1]);
                mma16816(sf[2 * nb + 1], ah, bl[2], bl[3]);
            }
        }

        float corr[2];
#pragma unroll
        for (int half = 0; half < 2; half++) {
            float mt = -1e30f;
#pragma unroll
            for (int ni = 0; ni < 16; ni++)
                mt = fmaxf(mt, fmaxf(sf[ni][2 * half], sf[ni][2 * half + 1]));
            mt *= scale;
            mt = fmaxf(mt, __shfl_xor_sync(0xffffffffu, mt, 1));
            mt = fmaxf(mt, __shfl_xor_sync(0xffffffffu, mt, 2));
            float mnew = fmaxf(mrow[half], mt);
            corr[half] = __expf(mrow[half] - mnew);
            mrow[half] = mnew;
            float sum = 0.f;
#pragma unroll
            for (int ni = 0; ni < 16; ni++) {
                float p0 = __expf(sf[ni][2 * half]     * scale - mnew);
                float p1 = __expf(sf[ni][2 * half + 1] * scale - mnew);
                sf[ni][2 * half]     = p0;
                sf[ni][2 * half + 1] = p1;
                sum += p0 + p1;
            }
            sum += __shfl_xor_sync(0xffffffffu, sum, 1);
            sum += __shfl_xor_sync(0xffffffffu, sum, 2);
            lrow[half] = lrow[half] * corr[half] + sum;
        }

#pragma unroll
        for (int ni = 0; ni < 16; ni++) {
            of[ni][0] *= corr[0]; of[ni][1] *= corr[0];
            of[ni][2] *= corr[1]; of[ni][3] *= corr[1];
        }

#pragma unroll
        for (int s = 0; s < 8; s++) {
            uint32_t ph[4], pl[4];
#pragma unroll
            for (int q = 0; q < 4; q++) {
                int cell = 2 * s + (q >> 1);
                float p0 = sf[cell][(q & 1) * 2];
                float p1 = sf[cell][(q & 1) * 2 + 1];
                uint32_t hpk = packbf(p0, p1);
                __nv_bfloat162 hb = *reinterpret_cast<__nv_bfloat162*>(&hpk);
                ph[q] = hpk;
                pl[q] = packbf(p0 - __bfloat162float(hb.x),
                               p1 - __bfloat162float(hb.y));
            }
#pragma unroll
            for (int nb = 0; nb < 8; nb++) {
                uint32_t vh[4], vl[4];
                uint32_t vo = toff + (uint32_t)(16 * s * FST) * 2 + (uint32_t)(nb * 16) * 2;
                ldm4t(vh, sVhi + vo);
                ldm4t(vl, sVlo + vo);
                mma16816(of[2 * nb],     ph, vh[0], vh[1]);
                mma16816(of[2 * nb + 1], ph, vh[2], vh[3]);
                mma16816(of[2 * nb],     pl, vh[0], vh[1]);
                mma16816(of[2 * nb + 1], pl, vh[2], vh[3]);
                mma16816(of[2 * nb],     ph, vl[0], vl[1]);
                mma16816(of[2 * nb + 1], ph, vl[2], vl[3]);
            }
        }
    }

    float inv0 = 1.0f / lrow[0], inv1 = 1.0f / lrow[1];
    int r0 = q0 + 16 * warp + (lane >> 2);
    int r1 = r0 + 8;
    size_t arow0 = ((size_t)b * Sq + r0) * (size_t)HIDc + (size_t)h * HDc;
    size_t arow1 = ((size_t)b * Sq + r1) * (size_t)HIDc + (size_t)h * HDc;
#pragma unroll
    for (int ni = 0; ni < 16; ni++) {
        int d0 = 8 * ni + (lane & 3) * 2;
        {
            float v0 = of[ni][0] * inv0, v1 = of[ni][1] * inv0;
            uint32_t hp = packbf(v0, v1);
            __nv_bfloat162 hb = *reinterpret_cast<__nv_bfloat162*>(&hp);
            uint32_t lp = packbf(v0 - __bfloat162float(hb.x), v1 - __bfloat162float(hb.y));
            *reinterpret_cast<uint32_t*>(ahi + arow0 + d0) = hp;
            *reinterpret_cast<uint32_t*>(alo + arow0 + d0) = lp;
        }
        {
            float v0 = of[ni][2] * inv1, v1 = of[ni][3] * inv1;
            uint32_t hp = packbf(v0, v1);
            __nv_bfloat162 hb = *reinterpret_cast<__nv_bfloat162*>(&hp);
            uint32_t lp = packbf(v0 - __bfloat162float(hb.x), v1 - __bfloat162float(hb.y));
            *reinterpret_cast<uint32_t*>(ahi + arow1 + d0) = hp;
            *reinterpret_cast<uint32_t*>(alo + arow1 + d0) = lp;
        }
    }
}

// ---------------------------------------------------------------------------
extern "C" void kernel_launch(void* const* d_in, const int* in_sizes, int n_in,
                              void* d_out, int out_size)
{
    const float* hidden = (const float*)d_in[0];
    const float* cosp   = (const float*)d_in[1];
    const float* sinp   = (const float*)d_in[2];
    const float* Wq     = (const float*)d_in[3];
    const float* bq     = (const float*)d_in[4];
    const float* Wk     = (const float*)d_in[5];
    const float* bk     = (const float*)d_in[6];
    const float* Wv     = (const float*)d_in[7];
    const float* bv     = (const float*)d_in[8];
    const float* Wo     = (const float*)d_in[9];
    float* out = (float*)d_out;

    float *qb, *kb, *vb;
    __nv_bfloat16 *ahi, *alo, *bhi, *blo;
    cudaGetSymbolAddress((void**)&qb, g_Q);
    cudaGetSymbolAddress((void**)&kb, g_K);
    cudaGetSymbolAddress((void**)&vb, g_V);
    cudaGetSymbolAddress((void**)&ahi, g_Ahi);
    cudaGetSymbolAddress((void**)&alo, g_Alo);
    cudaGetSymbolAddress((void**)&bhi, g_Bhi);
    cudaGetSymbolAddress((void**)&blo, g_Blo);

    cudaFuncSetAttribute(gemm_mma<0>, cudaFuncAttributeMaxDynamicSharedMemorySize, GSMEM);
    cudaFuncSetAttribute(gemm_mma<1>, cudaFuncAttributeMaxDynamicSharedMemorySize, GSMEM);
    cudaFuncSetAttribute(flash_kernel, cudaFuncAttributeMaxDynamicSharedMemorySize, FL_SMEM);

    // 1. prep
    prep_kernel<<<16384 + 16384 + 4096 + 4096, 256>>>(hidden, ahi, alo, Wq, Wk, Wv, bhi, blo);

    // 2. fused QKV projection
    gemm_mma<1><<<dim3(NQKV / 128, 32), 256, GSMEM>>>(ahi, alo, bhi, blo,
                                                      bq, bk, bv, qb, kb, vb, NQKV);

    // 3. RoPE
    {
        int tot = Bc * NHc * Sq * 64 + Bc * NKVc * Sq * 64;
        rope2_kernel<<<(tot + 255) / 256, 256>>>(qb, kb, cosp, sinp);
    }

    // 4. tensor-core flash attention  <-- profiled
    flash_kernel<<<dim3(Sq / 128, NHc, Bc), 256, FL_SMEM>>>(qb, kb, vb, ahi, alo);

    // 5-6. output projection
    tsplit_kernel<<<16384, 256>>>(Wo, bhi, blo);
    gemm_mma<0><<<dim3(32, 32), 256, GSMEM>>>(ahi, alo, bhi, blo,
                                              nullptr, nullptr, nullptr,
                                              out, nullptr, nullptr, 4096);
}